// round 1
// baseline (speedup 1.0000x reference)
#include <cuda_runtime.h>
#include <math.h>

#define NT  4096
#define DD  1024
#define HFd 2048
#define HSd 4096
#define NE  8
#define NF  4

// ---------------- device scratch (no allocations allowed) ----------------
__device__ int   g_cnt[NE];
__device__ int   g_idx[NE][NT];
__device__ float g_wt[NE][NT];

// one big scratch: XG | HA_F | HB_F | HA_S | HB_S | Y   (floats)
#define OFF_XG   0ull
#define OFF_HAF  (OFF_XG  + 8ull*NT*DD)
#define OFF_HBF  (OFF_HAF + 4ull*NT*HFd)
#define OFF_HAS  (OFF_HBF + 4ull*NT*HFd)
#define OFF_HBS  (OFF_HAS + 4ull*NT*HSd)
#define OFF_Y    (OFF_HBS + 4ull*NT*HSd)
#define SCRATCH_FLOATS (OFF_Y + 8ull*NT*DD)
__device__ float g_scratch[SCRATCH_FLOATS];

// ---------------- reset: zero output + counts ----------------
__global__ void reset_kernel(float* __restrict__ out) {
    size_t i = (size_t)blockIdx.x * 256u + threadIdx.x;
    out[i] = 0.f;
    if (i < NE) g_cnt[i] = 0;
}

// ---------------- router: logits -> softmax -> top2 -> slot lists ----------------
__global__ void router_kernel(const float* __restrict__ x,
                              const float* __restrict__ rw) {
    int gw   = (int)((blockIdx.x * blockDim.x + threadIdx.x) >> 5);
    int lane = threadIdx.x & 31;
    if (gw >= NT) return;
    const float* xr = x + (size_t)gw * DD;

    float l[NE];
#pragma unroll
    for (int e = 0; e < NE; e++) {
        const float* wr = rw + (size_t)e * DD;
        float s = 0.f;
        for (int d = lane; d < DD; d += 32) s = fmaf(xr[d], wr[d], s);
#pragma unroll
        for (int o = 16; o; o >>= 1) s += __shfl_xor_sync(0xffffffffu, s, o);
        l[e] = s;
    }
    if (lane == 0) {
        float m = l[0];
#pragma unroll
        for (int e = 1; e < NE; e++) m = fmaxf(m, l[e]);
        float w[NE], sum = 0.f;
#pragma unroll
        for (int e = 0; e < NE; e++) { w[e] = expf(l[e] - m); sum += w[e]; }
        float inv = 1.f / sum;
#pragma unroll
        for (int e = 0; e < NE; e++) w[e] *= inv;

        int i1 = 0;
#pragma unroll
        for (int e = 1; e < NE; e++) if (w[e] > w[i1]) i1 = e;
        int i2 = (i1 == 0) ? 1 : 0;
#pragma unroll
        for (int e = 0; e < NE; e++) if (e != i1 && w[e] > w[i2]) i2 = e;

        float tw = fmaxf(w[i1] + w[i2], 1e-9f);
        float w1 = w[i1] / tw, w2 = w[i2] / tw;

        int p1 = atomicAdd(&g_cnt[i1], 1);
        g_idx[i1][p1] = gw; g_wt[i1][p1] = w1;
        int p2 = atomicAdd(&g_cnt[i2], 1);
        g_idx[i2][p2] = gw; g_wt[i2][p2] = w2;
    }
}

// ---------------- gather: RMSNorm (fractal) or copy (switch) into contiguous rows ----------------
__global__ void gather_kernel(const float* __restrict__ x,
                              const float* __restrict__ frms) {
    int e = blockIdx.y;
    int s = blockIdx.x;
    if (s >= g_cnt[e]) return;
    int t = g_idx[e][s];
    int tid = threadIdx.x;  // 256 threads, 4 floats each
    const float4* xr = (const float4*)(x + (size_t)t * DD);
    float4* dst = (float4*)(g_scratch + OFF_XG + ((size_t)e * NT + s) * DD);

    float4 v = xr[tid];
    if (e < NF) {
        float ss = v.x*v.x + v.y*v.y + v.z*v.z + v.w*v.w;
#pragma unroll
        for (int o = 16; o; o >>= 1) ss += __shfl_xor_sync(0xffffffffu, ss, o);
        __shared__ float red[8];
        if ((tid & 31) == 0) red[tid >> 5] = ss;
        __syncthreads();
        if (tid < 8) {
            float r = red[tid];
#pragma unroll
            for (int o = 4; o; o >>= 1) r += __shfl_xor_sync(0x000000ffu, r, o);
            if (tid == 0) red[0] = r;
        }
        __syncthreads();
        float scale = rsqrtf(red[0] * (1.f / DD) + 1e-6f);
        const float4* rm = (const float4*)(frms + (size_t)e * DD);
        float4 g = rm[tid];
        float4 o;
        o.x = v.x * scale * g.x; o.y = v.y * scale * g.y;
        o.z = v.z * scale * g.z; o.w = v.w * scale * g.w;
        dst[tid] = o;
    } else {
        dst[tid] = v;
    }
}

// ---------------- batched GEMM: C[m,n] = sum_k A[m,k] * B[n,k] ----------------
// A rows gathered-contiguous in g_scratch; B is a weight matrix [Nn, K] row-major.
// grid: (Nn/128, NT/128, nExperts). Early-exits on per-expert count.
__global__ void __launch_bounds__(256, 2)
gemm_tn(size_t offA, size_t strideA,
        const float* __restrict__ Bw, size_t strideB,
        size_t offC, size_t strideC,
        int cntOff, int K, int Nn) {
    const int z = blockIdx.z;
    const int cnt = g_cnt[cntOff + z];
    const int m0 = blockIdx.y * 128;
    if (m0 >= cnt) return;
    const int n0 = blockIdx.x * 128;

    const float* A = g_scratch + offA + (size_t)z * strideA;
    const float* B = Bw + (size_t)z * strideB;
    float*       C = g_scratch + offC + (size_t)z * strideC;

    __shared__ float As[8][128];
    __shared__ float Bs[8][128];

    const int tid  = threadIdx.x;
    const int arow = tid >> 1;
    const int acol = (tid & 1) * 4;
    const int tr   = tid / 16;   // 0..15 -> rows
    const int tc   = tid % 16;   // 0..15 -> cols

    float acc[8][8];
#pragma unroll
    for (int i = 0; i < 8; i++)
#pragma unroll
        for (int j = 0; j < 8; j++) acc[i][j] = 0.f;

    const int nK = K >> 3;
    for (int kb = 0; kb < nK; kb++) {
        const int k0 = kb << 3;
        float4 av = make_float4(0.f, 0.f, 0.f, 0.f);
        int gm = m0 + arow;
        if (gm < cnt) av = *(const float4*)&A[(size_t)gm * K + k0 + acol];
        As[acol + 0][arow] = av.x; As[acol + 1][arow] = av.y;
        As[acol + 2][arow] = av.z; As[acol + 3][arow] = av.w;

        float4 bv = *(const float4*)&B[(size_t)(n0 + arow) * K + k0 + acol];
        Bs[acol + 0][arow] = bv.x; Bs[acol + 1][arow] = bv.y;
        Bs[acol + 2][arow] = bv.z; Bs[acol + 3][arow] = bv.w;
        __syncthreads();

#pragma unroll
        for (int k = 0; k < 8; k++) {
            float4 a0 = *(const float4*)&As[k][tr * 8];
            float4 a1 = *(const float4*)&As[k][tr * 8 + 4];
            float4 b0 = *(const float4*)&Bs[k][tc * 8];
            float4 b1 = *(const float4*)&Bs[k][tc * 8 + 4];
            float af[8] = {a0.x, a0.y, a0.z, a0.w, a1.x, a1.y, a1.z, a1.w};
            float bf[8] = {b0.x, b0.y, b0.z, b0.w, b1.x, b1.y, b1.z, b1.w};
#pragma unroll
            for (int i = 0; i < 8; i++)
#pragma unroll
                for (int j = 0; j < 8; j++)
                    acc[i][j] = fmaf(af[i], bf[j], acc[i][j]);
        }
        __syncthreads();
    }

#pragma unroll
    for (int i = 0; i < 8; i++) {
        int gm = m0 + tr * 8 + i;
        if (gm < cnt) {
            float* crow = C + (size_t)gm * Nn + n0 + tc * 8;
            *(float4*)crow       = make_float4(acc[i][0], acc[i][1], acc[i][2], acc[i][3]);
            *(float4*)(crow + 4) = make_float4(acc[i][4], acc[i][5], acc[i][6], acc[i][7]);
        }
    }
}

// ---------------- silu(a) * b, in place into A ----------------
__global__ void act_kernel(size_t offA, size_t offB, size_t stride, int cntOff, int H) {
    int z = blockIdx.y;
    size_t i = (size_t)blockIdx.x * 256u + threadIdx.x;
    int cnt = g_cnt[cntOff + z];
    if (i >= (size_t)cnt * H) return;
    float* A = g_scratch + offA + (size_t)z * stride;
    const float* B = g_scratch + offB + (size_t)z * stride;
    float a = A[i], b = B[i];
    A[i] = (a / (1.f + expf(-a))) * b;
}

// ---------------- scatter epilogues ----------------
__global__ void scatter_frac(const float* __restrict__ x,
                             const float* __restrict__ gamma,
                             float* __restrict__ out) {
    int e = blockIdx.y;
    size_t i = (size_t)blockIdx.x * 256u + threadIdx.x;   // over NT*DD
    int s = (int)(i / DD);
    if (s >= g_cnt[e]) return;
    int d = (int)(i % DD);
    int t = g_idx[e][s];
    float w = g_wt[e][s];
    float xn = g_scratch[OFF_XG + (size_t)e * NT * DD + i];
    float y  = g_scratch[OFF_Y  + (size_t)e * NT * DD + i];
    float val = gamma[(size_t)e * DD + d] * (xn + y) + x[(size_t)t * DD + d];
    atomicAdd(&out[(size_t)t * DD + d], w * val);
}

__global__ void scatter_sw(float* __restrict__ out) {
    int j = blockIdx.y;
    int e = NF + j;
    size_t i = (size_t)blockIdx.x * 256u + threadIdx.x;
    int s = (int)(i / DD);
    if (s >= g_cnt[e]) return;
    int d = (int)(i % DD);
    int t = g_idx[e][s];
    float w = g_wt[e][s];
    float y = g_scratch[OFF_Y + (size_t)e * NT * DD + i];
    atomicAdd(&out[(size_t)t * DD + d], w * y);
}

// ---------------- launch ----------------
extern "C" void kernel_launch(void* const* d_in, const int* in_sizes, int n_in,
                              void* d_out, int out_size) {
    const float* x          = (const float*)d_in[0];
    const float* router_w   = (const float*)d_in[1];
    const float* frac_rms   = (const float*)d_in[2];
    const float* frac_w1    = (const float*)d_in[3];
    const float* frac_w2    = (const float*)d_in[4];
    const float* frac_w3    = (const float*)d_in[5];
    const float* frac_gamma = (const float*)d_in[6];
    const float* sw_w1      = (const float*)d_in[7];
    const float* sw_w2      = (const float*)d_in[8];
    const float* sw_w3      = (const float*)d_in[9];
    float* out = (float*)d_out;

    (void)in_sizes; (void)n_in; (void)out_size;

    reset_kernel<<<(NT * DD) / 256, 256>>>(out);
    router_kernel<<<NT / 8, 256>>>(x, router_w);
    gather_kernel<<<dim3(NT, NE), 256>>>(x, frac_rms);

    // fractal experts: xn @ w1^T, xn @ w3^T   (K=D, Nn=HF)
    gemm_tn<<<dim3(HFd / 128, NT / 128, NF), 256>>>(
        OFF_XG, (size_t)NT * DD, frac_w1, (size_t)HFd * DD,
        OFF_HAF, (size_t)NT * HFd, 0, DD, HFd);
    gemm_tn<<<dim3(HFd / 128, NT / 128, NF), 256>>>(
        OFF_XG, (size_t)NT * DD, frac_w3, (size_t)HFd * DD,
        OFF_HBF, (size_t)NT * HFd, 0, DD, HFd);

    // switch experts: x @ w1^T, x @ w3^T   (K=D, Nn=HS)
    gemm_tn<<<dim3(HSd / 128, NT / 128, NF), 256>>>(
        OFF_XG + 4ull * NT * DD, (size_t)NT * DD, sw_w1, (size_t)HSd * DD,
        OFF_HAS, (size_t)NT * HSd, 4, DD, HSd);
    gemm_tn<<<dim3(HSd / 128, NT / 128, NF), 256>>>(
        OFF_XG + 4ull * NT * DD, (size_t)NT * DD, sw_w3, (size_t)HSd * DD,
        OFF_HBS, (size_t)NT * HSd, 4, DD, HSd);

    // silu * gate
    act_kernel<<<dim3((NT * HFd) / 256, NF), 256>>>(OFF_HAF, OFF_HBF, (size_t)NT * HFd, 0, HFd);
    act_kernel<<<dim3((NT * HSd) / 256, NF), 256>>>(OFF_HAS, OFF_HBS, (size_t)NT * HSd, 4, HSd);

    // down-projection: h @ w2^T  (K=H, Nn=D)
    gemm_tn<<<dim3(DD / 128, NT / 128, NF), 256>>>(
        OFF_HAF, (size_t)NT * HFd, frac_w2, (size_t)DD * HFd,
        OFF_Y, (size_t)NT * DD, 0, HFd, DD);
    gemm_tn<<<dim3(DD / 128, NT / 128, NF), 256>>>(
        OFF_HAS, (size_t)NT * HSd, sw_w2, (size_t)DD * HSd,
        OFF_Y + 4ull * NT * DD, (size_t)NT * DD, 4, HSd, DD);

    // weighted scatter back to tokens
    scatter_frac<<<dim3((NT * DD) / 256, NF), 256>>>(x, frac_gamma, out);
    scatter_sw<<<dim3((NT * DD) / 256, NF), 256>>>(out);
}

// round 3
// speedup vs baseline: 2.5331x; 2.5331x over previous
#include <cuda_runtime.h>
#include <cuda_bf16.h>
#include <cstdint>
#include <math.h>

#define NT  4096
#define DD  1024
#define HFd 2048
#define HSd 4096
#define NE  8
#define NF  4

// ---------------- routing state ----------------
__device__ int   g_cnt[NE];
__device__ int   g_idx[NE][NT];
__device__ float g_wt[NE][NT];

// ---------------- scratch (fp32, float offsets) ----------------
constexpr size_t F_XG  = 0;                         // [NE][NT][DD] gathered rows
constexpr size_t F_CAF = F_XG  + 8ull * NT * DD;    // [NF][NT][HF] up1 (then act, in place)
constexpr size_t F_CBF = F_CAF + 4ull * NT * HFd;   // [NF][NT][HF] up3
constexpr size_t F_CAS = F_CBF + 4ull * NT * HFd;   // [4][NT][HS]
constexpr size_t F_CBS = F_CAS + 4ull * NT * HSd;
constexpr size_t F_Y   = F_CBS + 4ull * NT * HSd;   // [NE][NT][DD] down-proj out
constexpr size_t SCRATCH_FLOATS = F_Y + 8ull * NT * DD;
__device__ float g_scratch[SCRATCH_FLOATS];

// ---------------- helpers ----------------
__device__ __forceinline__ uint32_t smem_u32(const void* p) {
    uint32_t a;
    asm("{ .reg .u64 t; cvta.to.shared.u64 t, %1; cvt.u32.u64 %0, t; }" : "=r"(a) : "l"(p));
    return a;
}
__device__ __forceinline__ void ldm4(uint32_t* r, uint32_t addr) {
    asm volatile("ldmatrix.sync.aligned.m8n8.x4.shared.b16 {%0,%1,%2,%3}, [%4];"
        : "=r"(r[0]), "=r"(r[1]), "=r"(r[2]), "=r"(r[3]) : "r"(addr));
}
__device__ __forceinline__ void mma16816(float* d, const uint32_t* a, uint32_t b0, uint32_t b1) {
    asm volatile("mma.sync.aligned.m16n8k16.row.col.f32.bf16.bf16.f32 "
        "{%0,%1,%2,%3}, {%4,%5,%6,%7}, {%8,%9}, {%0,%1,%2,%3};"
        : "+f"(d[0]), "+f"(d[1]), "+f"(d[2]), "+f"(d[3])
        : "r"(a[0]), "r"(a[1]), "r"(a[2]), "r"(a[3]), "r"(b0), "r"(b1));
}

// ---------------- reset ----------------
__global__ void reset_kernel(float* __restrict__ out) {
    size_t i = (size_t)blockIdx.x * 256u + threadIdx.x;
    out[i] = 0.f;
    if (i < NE) g_cnt[i] = 0;
}

// ---------------- router ----------------
__global__ void router_kernel(const float* __restrict__ x, const float* __restrict__ rw) {
    int gw = (int)((blockIdx.x * blockDim.x + threadIdx.x) >> 5);
    int lane = threadIdx.x & 31;
    if (gw >= NT) return;
    const float* xr = x + (size_t)gw * DD;
    float l[NE];
#pragma unroll
    for (int e = 0; e < NE; e++) {
        const float* wr = rw + (size_t)e * DD;
        float s = 0.f;
        for (int d = lane; d < DD; d += 32) s = fmaf(xr[d], wr[d], s);
#pragma unroll
        for (int o = 16; o; o >>= 1) s += __shfl_xor_sync(0xffffffffu, s, o);
        l[e] = s;
    }
    if (lane == 0) {
        float m = l[0];
#pragma unroll
        for (int e = 1; e < NE; e++) m = fmaxf(m, l[e]);
        float w[NE], sum = 0.f;
#pragma unroll
        for (int e = 0; e < NE; e++) { w[e] = expf(l[e] - m); sum += w[e]; }
        float inv = 1.f / sum;
#pragma unroll
        for (int e = 0; e < NE; e++) w[e] *= inv;
        int i1 = 0;
#pragma unroll
        for (int e = 1; e < NE; e++) if (w[e] > w[i1]) i1 = e;
        int i2 = (i1 == 0) ? 1 : 0;
#pragma unroll
        for (int e = 0; e < NE; e++) if (e != i1 && w[e] > w[i2]) i2 = e;
        float tw = fmaxf(w[i1] + w[i2], 1e-9f);
        int p1 = atomicAdd(&g_cnt[i1], 1);
        g_idx[i1][p1] = gw; g_wt[i1][p1] = w[i1] / tw;
        int p2 = atomicAdd(&g_cnt[i2], 1);
        g_idx[i2][p2] = gw; g_wt[i2][p2] = w[i2] / tw;
    }
}

// ---------------- gather: RMSNorm (fractal) / copy (switch), fp32 out ----------------
__global__ void gather_kernel(const float* __restrict__ x, const float* __restrict__ frms) {
    int e = blockIdx.y;
    int s = blockIdx.x;
    if (s >= g_cnt[e]) return;
    int t = g_idx[e][s];
    int tid = threadIdx.x;
    float4 v = ((const float4*)(x + (size_t)t * DD))[tid];
    float4* dst = (float4*)(g_scratch + F_XG + ((size_t)e * NT + s) * DD);
    if (e < NF) {
        float ss = v.x * v.x + v.y * v.y + v.z * v.z + v.w * v.w;
#pragma unroll
        for (int o = 16; o; o >>= 1) ss += __shfl_xor_sync(0xffffffffu, ss, o);
        __shared__ float red[8];
        if ((tid & 31) == 0) red[tid >> 5] = ss;
        __syncthreads();
        if (tid < 8) {
            float r = red[tid];
#pragma unroll
            for (int o = 4; o; o >>= 1) r += __shfl_xor_sync(0x000000ffu, r, o);
            if (tid == 0) red[0] = r;
        }
        __syncthreads();
        float scale = rsqrtf(red[0] * (1.f / DD) + 1e-6f);
        float4 g = ((const float4*)(frms + (size_t)e * DD))[tid];
        float4 o;
        o.x = v.x * scale * g.x; o.y = v.y * scale * g.y;
        o.z = v.z * scale * g.z; o.w = v.w * scale * g.w;
        dst[tid] = o;
    } else {
        dst[tid] = v;
    }
}

// ---------------- tensor-core GEMM (mma.sync, bf16 hi/lo x3 split) ----------------
// C[m,n] = sum_k A[m,k] * B[n,k]; A fp32 in g_scratch, B fp32 weights (gmem),
// converted to bf16 hi/lo during the smem staging.
#define SROW   80                       // smem bytes per 32-elem bf16 row (padded)
#define MATB   (128 * SROW)             // 10240 B per matrix tile
#define BUFB   (4 * MATB)               // Ah | Al | Bh | Bl
#define SMEM_DYN (2 * BUFB)             // double buffered: 81920 B

__device__ __forceinline__ void cvt_sts8(uint32_t dstHi, const float* v) {
    union { __nv_bfloat162 h2[4]; uint4 u; } H, L;
#pragma unroll
    for (int j = 0; j < 4; j++) {
        float2 p = make_float2(v[2 * j], v[2 * j + 1]);
        __nv_bfloat162 hh = __float22bfloat162_rn(p);
        float2 hf = __bfloat1622float2(hh);
        __nv_bfloat162 ll = __float22bfloat162_rn(make_float2(p.x - hf.x, p.y - hf.y));
        H.h2[j] = hh; L.h2[j] = ll;
    }
    asm volatile("st.shared.v4.b32 [%0], {%1,%2,%3,%4};"
        :: "r"(dstHi), "r"(H.u.x), "r"(H.u.y), "r"(H.u.z), "r"(H.u.w));
    asm volatile("st.shared.v4.b32 [%0], {%1,%2,%3,%4};"
        :: "r"(dstHi + MATB), "r"(L.u.x), "r"(L.u.y), "r"(L.u.z), "r"(L.u.w));
}

__global__ void __launch_bounds__(512, 1)
gemm_mma(size_t offA, size_t strideA,
         const float* __restrict__ Bw0, const float* __restrict__ Bw1, size_t strideB,
         size_t offC0, size_t offC1, size_t strideC,
         int cntBase, int K, int Nn, int dualB)
{
    const int z = blockIdx.z;
    const int e = dualB ? (z >> 1) : z;
    const int which = dualB ? (z & 1) : 0;
    const int cnt = g_cnt[cntBase + e];
    const int m0 = blockIdx.y * 128;
    if (m0 >= cnt) return;
    const int n0 = blockIdx.x * 128;

    const float* A  = g_scratch + offA + (size_t)e * strideA;
    const float* Bw = (which ? Bw1 : Bw0) + (size_t)e * strideB;
    float*       C  = g_scratch + (which ? offC1 : offC0) + (size_t)e * strideC;

    extern __shared__ char smem[];
    const uint32_t sb = smem_u32(smem);

    const int tid  = threadIdx.x;
    const int lane = tid & 31;
    const int wid  = tid >> 5;
    const int mr   = wid & 3;    // warp m tile (32 rows each)
    const int ncq  = wid >> 2;   // warp n tile (32 cols each)

    // staging: thread -> (row 0..127, 8-float k-group 0..3)
    const int lrow = tid >> 2;
    const int lgrp = tid & 3;
    const float* aSrc = A  + (size_t)(m0 + lrow) * K + lgrp * 8;
    const float* bSrc = Bw + (size_t)(n0 + lrow) * K + lgrp * 8;
    const uint32_t stsA = sb + (uint32_t)lrow * SROW + lgrp * 16;
    const uint32_t stsB = stsA + 2 * MATB;

    // ldmatrix lane addresses
    const uint32_t aBase = sb + (uint32_t)(mr * 32 + (lane & 15)) * SROW + ((lane >> 4) * 16);
    const int bnoff = (lane & 7) + ((lane >> 4) << 3);
    const uint32_t bBase = sb + 2 * MATB + (uint32_t)(ncq * 32 + bnoff) * SROW + (((lane >> 3) & 1) * 16);

    float acc[2][4][4];
#pragma unroll
    for (int i = 0; i < 2; i++)
#pragma unroll
        for (int j = 0; j < 4; j++)
#pragma unroll
            for (int q = 0; q < 4; q++) acc[i][j][q] = 0.f;

    float av[8], bv[8];
    // prologue: stage 0
    {
        float4 a0 = *(const float4*)aSrc, a1 = *(const float4*)(aSrc + 4);
        float4 b0 = *(const float4*)bSrc, b1 = *(const float4*)(bSrc + 4);
        av[0]=a0.x; av[1]=a0.y; av[2]=a0.z; av[3]=a0.w; av[4]=a1.x; av[5]=a1.y; av[6]=a1.z; av[7]=a1.w;
        bv[0]=b0.x; bv[1]=b0.y; bv[2]=b0.z; bv[3]=b0.w; bv[4]=b1.x; bv[5]=b1.y; bv[6]=b1.z; bv[7]=b1.w;
        cvt_sts8(stsA, av);
        cvt_sts8(stsB, bv);
    }
    __syncthreads();

    const int nst = K >> 5;
    for (int kc = 0; kc < nst; kc++) {
        const uint32_t bufo = (uint32_t)(kc & 1) * BUFB;
        const bool pre = (kc + 1) < nst;
        if (pre) {
            const float* ap = aSrc + (kc + 1) * 32;
            const float* bp = bSrc + (kc + 1) * 32;
            float4 a0 = *(const float4*)ap, a1 = *(const float4*)(ap + 4);
            float4 b0 = *(const float4*)bp, b1 = *(const float4*)(bp + 4);
            av[0]=a0.x; av[1]=a0.y; av[2]=a0.z; av[3]=a0.w; av[4]=a1.x; av[5]=a1.y; av[6]=a1.z; av[7]=a1.w;
            bv[0]=b0.x; bv[1]=b0.y; bv[2]=b0.z; bv[3]=b0.w; bv[4]=b1.x; bv[5]=b1.y; bv[6]=b1.z; bv[7]=b1.w;
        }
#pragma unroll
        for (int k16 = 0; k16 < 2; k16++) {
            uint32_t ah[2][4], al[2][4];
#pragma unroll
            for (int mt = 0; mt < 2; mt++) {
                ldm4(ah[mt], aBase + bufo + (uint32_t)(mt * 16) * SROW + k16 * 32);
                ldm4(al[mt], aBase + bufo + MATB + (uint32_t)(mt * 16) * SROW + k16 * 32);
            }
#pragma unroll
            for (int np = 0; np < 2; np++) {
                uint32_t bh[4], bl[4];
                ldm4(bh, bBase + bufo + (uint32_t)(np * 16) * SROW + k16 * 32);
                ldm4(bl, bBase + bufo + MATB + (uint32_t)(np * 16) * SROW + k16 * 32);
#pragma unroll
                for (int mt = 0; mt < 2; mt++)
#pragma unroll
                    for (int s = 0; s < 2; s++) {
                        float* d = acc[mt][np * 2 + s];
                        mma16816(d, ah[mt], bh[2 * s], bh[2 * s + 1]);
                        mma16816(d, ah[mt], bl[2 * s], bl[2 * s + 1]);
                        mma16816(d, al[mt], bh[2 * s], bh[2 * s + 1]);
                    }
            }
        }
        if (pre) {
            const uint32_t nb = (uint32_t)((kc + 1) & 1) * BUFB;
            cvt_sts8(stsA + nb, av);
            cvt_sts8(stsB + nb, bv);
        }
        __syncthreads();
    }

    // epilogue
#pragma unroll
    for (int mt = 0; mt < 2; mt++) {
        int r0 = m0 + mr * 32 + mt * 16 + (lane >> 2);
#pragma unroll
        for (int nt = 0; nt < 4; nt++) {
            int col = n0 + ncq * 32 + nt * 8 + 2 * (lane & 3);
            if (r0 < cnt)
                *(float2*)(C + (size_t)r0 * Nn + col) = make_float2(acc[mt][nt][0], acc[mt][nt][1]);
            if (r0 + 8 < cnt)
                *(float2*)(C + (size_t)(r0 + 8) * Nn + col) = make_float2(acc[mt][nt][2], acc[mt][nt][3]);
        }
    }
}

// ---------------- silu(a)*b -> a (in place, fp32) ----------------
__global__ void act_kernel(size_t offCA, size_t offCB, size_t stride, int cntBase, int H) {
    int z = blockIdx.y;
    size_t i = (size_t)blockIdx.x * 256u + threadIdx.x;
    if (i >= (size_t)g_cnt[cntBase + z] * H) return;
    float* Aq = g_scratch + offCA + (size_t)z * stride;
    const float* Bq = g_scratch + offCB + (size_t)z * stride;
    float a = Aq[i], b = Bq[i];
    Aq[i] = (a / (1.f + expf(-a))) * b;
}

// ---------------- scatter epilogues ----------------
__global__ void scatter_frac(const float* __restrict__ x, const float* __restrict__ gamma,
                             float* __restrict__ out) {
    int e = blockIdx.y;
    size_t i = (size_t)blockIdx.x * 256u + threadIdx.x;
    int s = (int)(i / DD);
    if (s >= g_cnt[e]) return;
    int d = (int)(i % DD);
    int t = g_idx[e][s];
    float w = g_wt[e][s];
    size_t base = (size_t)e * NT * DD + i;
    float xn = g_scratch[F_XG + base];
    float y  = g_scratch[F_Y + base];
    float val = gamma[(size_t)e * DD + d] * (xn + y) + x[(size_t)t * DD + d];
    atomicAdd(&out[(size_t)t * DD + d], w * val);
}

__global__ void scatter_sw(float* __restrict__ out) {
    int j = blockIdx.y;
    int e = NF + j;
    size_t i = (size_t)blockIdx.x * 256u + threadIdx.x;
    int s = (int)(i / DD);
    if (s >= g_cnt[e]) return;
    int t = g_idx[e][s];
    float w = g_wt[e][s];
    float y = g_scratch[F_Y + (size_t)e * NT * DD + i];
    atomicAdd(&out[(size_t)t * DD + (i % DD)], w * y);
}

// ---------------- launch ----------------
extern "C" void kernel_launch(void* const* d_in, const int* in_sizes, int n_in,
                              void* d_out, int out_size) {
    const float* x          = (const float*)d_in[0];
    const float* router_w   = (const float*)d_in[1];
    const float* frac_rms   = (const float*)d_in[2];
    const float* frac_w1    = (const float*)d_in[3];
    const float* frac_w2    = (const float*)d_in[4];
    const float* frac_w3    = (const float*)d_in[5];
    const float* frac_gamma = (const float*)d_in[6];
    const float* sw_w1      = (const float*)d_in[7];
    const float* sw_w2      = (const float*)d_in[8];
    const float* sw_w3      = (const float*)d_in[9];
    float* out = (float*)d_out;
    (void)in_sizes; (void)n_in; (void)out_size;

    cudaFuncSetAttribute(gemm_mma, cudaFuncAttributeMaxDynamicSharedMemorySize, SMEM_DYN);

    reset_kernel<<<(NT * DD) / 256, 256>>>(out);
    router_kernel<<<NT / 8, 256>>>(x, router_w);
    gather_kernel<<<dim3(NT, NE), 256>>>(x, frac_rms);

    // fractal up: xn @ w1^T / xn @ w3^T   (dualB: z = 2e + which)
    gemm_mma<<<dim3(HFd / 128, NT / 128, 2 * NF), 512, SMEM_DYN>>>(
        F_XG, (size_t)NT * DD,
        frac_w1, frac_w3, (size_t)HFd * DD,
        F_CAF, F_CBF, (size_t)NT * HFd,
        0, DD, HFd, 1);
    // switch up
    gemm_mma<<<dim3(HSd / 128, NT / 128, 8), 512, SMEM_DYN>>>(
        F_XG + 4ull * NT * DD, (size_t)NT * DD,
        sw_w1, sw_w3, (size_t)HSd * DD,
        F_CAS, F_CBS, (size_t)NT * HSd,
        4, DD, HSd, 1);

    // silu * gate (in place into CA)
    act_kernel<<<dim3((int)((size_t)NT * HFd / 256), NF), 256>>>(F_CAF, F_CBF, (size_t)NT * HFd, 0, HFd);
    act_kernel<<<dim3((int)((size_t)NT * HSd / 256), 4), 256>>>(F_CAS, F_CBS, (size_t)NT * HSd, 4, HSd);

    // fractal down: h @ w2^T
    gemm_mma<<<dim3(DD / 128, NT / 128, NF), 512, SMEM_DYN>>>(
        F_CAF, (size_t)NT * HFd,
        frac_w2, frac_w2, (size_t)DD * HFd,
        F_Y, F_Y, (size_t)NT * DD,
        0, HFd, DD, 0);
    // switch down
    gemm_mma<<<dim3(DD / 128, NT / 128, 4), 512, SMEM_DYN>>>(
        F_CAS, (size_t)NT * HSd,
        sw_w2, sw_w2, (size_t)DD * HSd,
        F_Y + 4ull * NT * DD, F_Y + 4ull * NT * DD, (size_t)NT * DD,
        4, HSd, DD, 0);

    scatter_frac<<<dim3((NT * DD) / 256, NF), 256>>>(x, frac_gamma, out);
    scatter_sw<<<dim3((NT * DD) / 256, 4), 256>>>(out);
}

// round 4
// speedup vs baseline: 2.6344x; 1.0400x over previous
#include <cuda_runtime.h>
#include <cuda_bf16.h>
#include <cstdint>
#include <math.h>

#define NT  4096
#define DD  1024
#define HFd 2048
#define HSd 4096
#define NE  8
#define NF  4

// ---------------- routing state ----------------
__device__ int   g_cnt[NE];
__device__ int   g_idx[NE][NT];
__device__ float g_wt[NE][NT];

// ---------------- scratch (fp32, float offsets) ----------------
constexpr size_t F_XG  = 0;                         // [NE][NT][DD] gathered rows
constexpr size_t F_CAF = F_XG  + 8ull * NT * DD;    // [NF][NT][HF] up1 (then act, in place)
constexpr size_t F_CBF = F_CAF + 4ull * NT * HFd;   // [NF][NT][HF] up3
constexpr size_t F_CAS = F_CBF + 4ull * NT * HFd;   // [4][NT][HS]
constexpr size_t F_CBS = F_CAS + 4ull * NT * HSd;
constexpr size_t F_Y   = F_CBS + 4ull * NT * HSd;   // [NE][NT][DD] down-proj out
constexpr size_t SCRATCH_FLOATS = F_Y + 8ull * NT * DD;
__device__ float g_scratch[SCRATCH_FLOATS];

// ---------------- helpers ----------------
__device__ __forceinline__ uint32_t smem_u32(const void* p) {
    uint32_t a;
    asm("{ .reg .u64 t; cvta.to.shared.u64 t, %1; cvt.u32.u64 %0, t; }" : "=r"(a) : "l"(p));
    return a;
}
__device__ __forceinline__ void ldm4(uint32_t* r, uint32_t addr) {
    asm volatile("ldmatrix.sync.aligned.m8n8.x4.shared.b16 {%0,%1,%2,%3}, [%4];"
        : "=r"(r[0]), "=r"(r[1]), "=r"(r[2]), "=r"(r[3]) : "r"(addr));
}
__device__ __forceinline__ void mma16816(float* d, const uint32_t* a, uint32_t b0, uint32_t b1) {
    asm volatile("mma.sync.aligned.m16n8k16.row.col.f32.bf16.bf16.f32 "
        "{%0,%1,%2,%3}, {%4,%5,%6,%7}, {%8,%9}, {%0,%1,%2,%3};"
        : "+f"(d[0]), "+f"(d[1]), "+f"(d[2]), "+f"(d[3])
        : "r"(a[0]), "r"(a[1]), "r"(a[2]), "r"(a[3]), "r"(b0), "r"(b1));
}

// ---------------- reset ----------------
__global__ void reset_kernel(float* __restrict__ out) {
    size_t i = (size_t)blockIdx.x * 256u + threadIdx.x;
    out[i] = 0.f;
    if (i < NE) g_cnt[i] = 0;
}

// ---------------- router ----------------
__global__ void router_kernel(const float* __restrict__ x, const float* __restrict__ rw) {
    int gw = (int)((blockIdx.x * blockDim.x + threadIdx.x) >> 5);
    int lane = threadIdx.x & 31;
    if (gw >= NT) return;
    const float* xr = x + (size_t)gw * DD;
    float l[NE];
#pragma unroll
    for (int e = 0; e < NE; e++) {
        const float* wr = rw + (size_t)e * DD;
        float s = 0.f;
        for (int d = lane; d < DD; d += 32) s = fmaf(xr[d], wr[d], s);
#pragma unroll
        for (int o = 16; o; o >>= 1) s += __shfl_xor_sync(0xffffffffu, s, o);
        l[e] = s;
    }
    if (lane == 0) {
        float m = l[0];
#pragma unroll
        for (int e = 1; e < NE; e++) m = fmaxf(m, l[e]);
        float w[NE], sum = 0.f;
#pragma unroll
        for (int e = 0; e < NE; e++) { w[e] = expf(l[e] - m); sum += w[e]; }
        float inv = 1.f / sum;
#pragma unroll
        for (int e = 0; e < NE; e++) w[e] *= inv;
        int i1 = 0;
#pragma unroll
        for (int e = 1; e < NE; e++) if (w[e] > w[i1]) i1 = e;
        int i2 = (i1 == 0) ? 1 : 0;
#pragma unroll
        for (int e = 0; e < NE; e++) if (e != i1 && w[e] > w[i2]) i2 = e;
        float tw = fmaxf(w[i1] + w[i2], 1e-9f);
        int p1 = atomicAdd(&g_cnt[i1], 1);
        g_idx[i1][p1] = gw; g_wt[i1][p1] = w[i1] / tw;
        int p2 = atomicAdd(&g_cnt[i2], 1);
        g_idx[i2][p2] = gw; g_wt[i2][p2] = w[i2] / tw;
    }
}

// ---------------- gather: RMSNorm (fractal) / copy (switch), fp32 out ----------------
__global__ void gather_kernel(const float* __restrict__ x, const float* __restrict__ frms) {
    int e = blockIdx.y;
    int s = blockIdx.x;
    if (s >= g_cnt[e]) return;
    int t = g_idx[e][s];
    int tid = threadIdx.x;
    float4 v = ((const float4*)(x + (size_t)t * DD))[tid];
    float4* dst = (float4*)(g_scratch + F_XG + ((size_t)e * NT + s) * DD);
    if (e < NF) {
        float ss = v.x * v.x + v.y * v.y + v.z * v.z + v.w * v.w;
#pragma unroll
        for (int o = 16; o; o >>= 1) ss += __shfl_xor_sync(0xffffffffu, ss, o);
        __shared__ float red[8];
        if ((tid & 31) == 0) red[tid >> 5] = ss;
        __syncthreads();
        if (tid < 8) {
            float r = red[tid];
#pragma unroll
            for (int o = 4; o; o >>= 1) r += __shfl_xor_sync(0x000000ffu, r, o);
            if (tid == 0) red[0] = r;
        }
        __syncthreads();
        float scale = rsqrtf(red[0] * (1.f / DD) + 1e-6f);
        float4 g = ((const float4*)(frms + (size_t)e * DD))[tid];
        float4 o;
        o.x = v.x * scale * g.x; o.y = v.y * scale * g.y;
        o.z = v.z * scale * g.z; o.w = v.w * scale * g.w;
        dst[tid] = o;
    } else {
        dst[tid] = v;
    }
}

// ---------------- tensor-core GEMM (mma.sync) ----------------
// C[m,n] = sum_k A[m,k] * B[n,k]; fp32 sources converted to bf16 (hi/lo for
// NSPLIT=3, hi only for NSPLIT=1) during smem staging.
// CTA tile 128x256, 16 warps, warp tile 32x64, k-chunk 32, double buffered.
#define SROW    80
#define APLANE  (128 * SROW)            // 10240
#define BPLANE  (256 * SROW)            // 20480
#define OFF_BH  (2 * APLANE)            // 20480
#define STAGEB  (2 * APLANE + 2 * BPLANE)  // 61440
#define SMEM_DYN (2 * STAGEB)           // 122880

template<bool LO>
__device__ __forceinline__ void cvt_sts8(uint32_t dstHi, uint32_t loDelta, const float* v) {
    union { __nv_bfloat162 h2[4]; uint4 u; } H, L;
#pragma unroll
    for (int j = 0; j < 4; j++) {
        float2 p = make_float2(v[2 * j], v[2 * j + 1]);
        __nv_bfloat162 hh = __float22bfloat162_rn(p);
        H.h2[j] = hh;
        if (LO) {
            float2 hf = __bfloat1622float2(hh);
            L.h2[j] = __float22bfloat162_rn(make_float2(p.x - hf.x, p.y - hf.y));
        }
    }
    asm volatile("st.shared.v4.b32 [%0], {%1,%2,%3,%4};"
        :: "r"(dstHi), "r"(H.u.x), "r"(H.u.y), "r"(H.u.z), "r"(H.u.w));
    if (LO)
        asm volatile("st.shared.v4.b32 [%0], {%1,%2,%3,%4};"
            :: "r"(dstHi + loDelta), "r"(L.u.x), "r"(L.u.y), "r"(L.u.z), "r"(L.u.w));
}

template<int NSPLIT>
__global__ void __launch_bounds__(512, 1)
gemm_mma(size_t offA, size_t strideA,
         const float* __restrict__ Bw0, const float* __restrict__ Bw1, size_t strideB,
         size_t offC0, size_t offC1, size_t strideC,
         int cntBase, int K, int Nn, int dualB)
{
    const int z = blockIdx.z;
    const int e = dualB ? (z >> 1) : z;
    const int which = dualB ? (z & 1) : 0;
    const int cnt = g_cnt[cntBase + e];
    const int m0 = blockIdx.y * 128;
    if (m0 >= cnt) return;
    const int n0 = blockIdx.x * 256;

    const float* A  = g_scratch + offA + (size_t)e * strideA;
    const float* Bw = (which ? Bw1 : Bw0) + (size_t)e * strideB;
    float*       C  = g_scratch + (which ? offC1 : offC0) + (size_t)e * strideC;

    extern __shared__ char smem[];
    const uint32_t sb = smem_u32(smem);

    const int tid  = threadIdx.x;
    const int lane = tid & 31;
    const int wid  = tid >> 5;
    const int mr   = wid & 3;    // 4 m-warps of 32 rows
    const int nc   = wid >> 2;   // 4 n-warps of 64 cols

    // staging: A 128 rows x 32k : thread -> (row, 8-float group)
    const int lrow = tid >> 2;
    const int lgrp = tid & 3;
    const float* aSrc = A  + (size_t)(m0 + lrow) * K + lgrp * 8;
    const float* bSrc0 = Bw + (size_t)(n0 + lrow) * K + lgrp * 8;
    const float* bSrc1 = Bw + (size_t)(n0 + 128 + lrow) * K + lgrp * 8;
    const uint32_t stsA  = sb + (uint32_t)lrow * SROW + lgrp * 16;
    const uint32_t stsB0 = sb + OFF_BH + (uint32_t)lrow * SROW + lgrp * 16;
    const uint32_t stsB1 = stsB0 + 128u * SROW;

    // ldmatrix lane addresses
    const uint32_t aBase = sb + (uint32_t)(mr * 32 + (lane & 15)) * SROW + ((lane >> 4) * 16);
    const int bnoff = (lane & 7) + ((lane >> 4) << 3);
    const uint32_t bBase = sb + OFF_BH + (uint32_t)(nc * 64 + bnoff) * SROW + (((lane >> 3) & 1) * 16);

    float acc[2][8][4];
#pragma unroll
    for (int i = 0; i < 2; i++)
#pragma unroll
        for (int j = 0; j < 8; j++)
#pragma unroll
            for (int q = 0; q < 4; q++) acc[i][j][q] = 0.f;

    float av[8], bv[16];
    // prologue: stage 0
    {
        float4 t0 = *(const float4*)aSrc, t1 = *(const float4*)(aSrc + 4);
        *(float4*)&av[0] = t0; *(float4*)&av[4] = t1;
        t0 = *(const float4*)bSrc0; t1 = *(const float4*)(bSrc0 + 4);
        *(float4*)&bv[0] = t0; *(float4*)&bv[4] = t1;
        t0 = *(const float4*)bSrc1; t1 = *(const float4*)(bSrc1 + 4);
        *(float4*)&bv[8] = t0; *(float4*)&bv[12] = t1;
        cvt_sts8<NSPLIT == 3>(stsA, APLANE, av);
        cvt_sts8<NSPLIT == 3>(stsB0, BPLANE, &bv[0]);
        cvt_sts8<NSPLIT == 3>(stsB1, BPLANE, &bv[8]);
    }
    __syncthreads();

    const int nst = K >> 5;
    for (int kc = 0; kc < nst; kc++) {
        const uint32_t bufo = (uint32_t)(kc & 1) * STAGEB;
        const bool pre = (kc + 1) < nst;
        if (pre) {
            const float* ap = aSrc + (kc + 1) * 32;
            const float* bp0 = bSrc0 + (kc + 1) * 32;
            const float* bp1 = bSrc1 + (kc + 1) * 32;
            float4 t0 = *(const float4*)ap, t1 = *(const float4*)(ap + 4);
            *(float4*)&av[0] = t0; *(float4*)&av[4] = t1;
            t0 = *(const float4*)bp0; t1 = *(const float4*)(bp0 + 4);
            *(float4*)&bv[0] = t0; *(float4*)&bv[4] = t1;
            t0 = *(const float4*)bp1; t1 = *(const float4*)(bp1 + 4);
            *(float4*)&bv[8] = t0; *(float4*)&bv[12] = t1;
        }
#pragma unroll
        for (int k16 = 0; k16 < 2; k16++) {
            uint32_t ah[2][4], al[2][4];
#pragma unroll
            for (int mt = 0; mt < 2; mt++) {
                ldm4(ah[mt], aBase + bufo + (uint32_t)(mt * 16) * SROW + k16 * 32);
                if (NSPLIT == 3)
                    ldm4(al[mt], aBase + bufo + APLANE + (uint32_t)(mt * 16) * SROW + k16 * 32);
            }
#pragma unroll
            for (int np = 0; np < 4; np++) {
                uint32_t bh[4], bl[4];
                ldm4(bh, bBase + bufo + (uint32_t)(np * 16) * SROW + k16 * 32);
                if (NSPLIT == 3)
                    ldm4(bl, bBase + bufo + BPLANE + (uint32_t)(np * 16) * SROW + k16 * 32);
#pragma unroll
                for (int mt = 0; mt < 2; mt++)
#pragma unroll
                    for (int s = 0; s < 2; s++) {
                        float* d = acc[mt][np * 2 + s];
                        mma16816(d, ah[mt], bh[2 * s], bh[2 * s + 1]);
                        if (NSPLIT == 3) {
                            mma16816(d, ah[mt], bl[2 * s], bl[2 * s + 1]);
                            mma16816(d, al[mt], bh[2 * s], bh[2 * s + 1]);
                        }
                    }
            }
        }
        if (pre) {
            const uint32_t nb = (uint32_t)((kc + 1) & 1) * STAGEB;
            cvt_sts8<NSPLIT == 3>(stsA + nb, APLANE, av);
            cvt_sts8<NSPLIT == 3>(stsB0 + nb, BPLANE, &bv[0]);
            cvt_sts8<NSPLIT == 3>(stsB1 + nb, BPLANE, &bv[8]);
        }
        __syncthreads();
    }

    // epilogue
#pragma unroll
    for (int mt = 0; mt < 2; mt++) {
        int r0 = m0 + mr * 32 + mt * 16 + (lane >> 2);
#pragma unroll
        for (int j = 0; j < 8; j++) {
            int col = n0 + nc * 64 + j * 8 + 2 * (lane & 3);
            if (r0 < cnt)
                *(float2*)(C + (size_t)r0 * Nn + col) = make_float2(acc[mt][j][0], acc[mt][j][1]);
            if (r0 + 8 < cnt)
                *(float2*)(C + (size_t)(r0 + 8) * Nn + col) = make_float2(acc[mt][j][2], acc[mt][j][3]);
        }
    }
}

// ---------------- silu(a)*b -> a (in place, fp32) ----------------
__global__ void act_kernel(size_t offCA, size_t offCB, size_t stride, int cntBase, int H) {
    int z = blockIdx.y;
    size_t i = (size_t)blockIdx.x * 256u + threadIdx.x;
    if (i >= (size_t)g_cnt[cntBase + z] * H) return;
    float* Aq = g_scratch + offCA + (size_t)z * stride;
    const float* Bq = g_scratch + offCB + (size_t)z * stride;
    float a = Aq[i], b = Bq[i];
    Aq[i] = (a / (1.f + expf(-a))) * b;
}

// ---------------- scatter epilogues ----------------
__global__ void scatter_frac(const float* __restrict__ x, const float* __restrict__ gamma,
                             float* __restrict__ out) {
    int e = blockIdx.y;
    size_t i = (size_t)blockIdx.x * 256u + threadIdx.x;
    int s = (int)(i / DD);
    if (s >= g_cnt[e]) return;
    int d = (int)(i % DD);
    int t = g_idx[e][s];
    float w = g_wt[e][s];
    size_t base = (size_t)e * NT * DD + i;
    float xn = g_scratch[F_XG + base];
    float y  = g_scratch[F_Y + base];
    float val = gamma[(size_t)e * DD + d] * (xn + y) + x[(size_t)t * DD + d];
    atomicAdd(&out[(size_t)t * DD + d], w * val);
}

__global__ void scatter_sw(float* __restrict__ out) {
    int j = blockIdx.y;
    int e = NF + j;
    size_t i = (size_t)blockIdx.x * 256u + threadIdx.x;
    int s = (int)(i / DD);
    if (s >= g_cnt[e]) return;
    int t = g_idx[e][s];
    float w = g_wt[e][s];
    float y = g_scratch[F_Y + (size_t)e * NT * DD + i];
    atomicAdd(&out[(size_t)t * DD + (i % DD)], w * y);
}

// ---------------- launch ----------------
extern "C" void kernel_launch(void* const* d_in, const int* in_sizes, int n_in,
                              void* d_out, int out_size) {
    const float* x          = (const float*)d_in[0];
    const float* router_w   = (const float*)d_in[1];
    const float* frac_rms   = (const float*)d_in[2];
    const float* frac_w1    = (const float*)d_in[3];
    const float* frac_w2    = (const float*)d_in[4];
    const float* frac_w3    = (const float*)d_in[5];
    const float* frac_gamma = (const float*)d_in[6];
    const float* sw_w1      = (const float*)d_in[7];
    const float* sw_w2      = (const float*)d_in[8];
    const float* sw_w3      = (const float*)d_in[9];
    float* out = (float*)d_out;
    (void)in_sizes; (void)n_in; (void)out_size;

    cudaFuncSetAttribute(gemm_mma<3>, cudaFuncAttributeMaxDynamicSharedMemorySize, SMEM_DYN);
    cudaFuncSetAttribute(gemm_mma<1>, cudaFuncAttributeMaxDynamicSharedMemorySize, SMEM_DYN);

    reset_kernel<<<(NT * DD) / 256, 256>>>(out);
    router_kernel<<<NT / 8, 256>>>(x, router_w);
    gather_kernel<<<dim3(NT, NE), 256>>>(x, frac_rms);

    // fractal up (gamma-attenuated branch -> plain bf16): xn @ w1^T / w3^T
    gemm_mma<1><<<dim3(HFd / 256, NT / 128, 2 * NF), 512, SMEM_DYN>>>(
        F_XG, (size_t)NT * DD,
        frac_w1, frac_w3, (size_t)HFd * DD,
        F_CAF, F_CBF, (size_t)NT * HFd,
        0, DD, HFd, 1);
    // switch up (full hi/lo x3 split)
    gemm_mma<3><<<dim3(HSd / 256, NT / 128, 8), 512, SMEM_DYN>>>(
        F_XG + 4ull * NT * DD, (size_t)NT * DD,
        sw_w1, sw_w3, (size_t)HSd * DD,
        F_CAS, F_CBS, (size_t)NT * HSd,
        4, DD, HSd, 1);

    // silu * gate (in place into CA)
    act_kernel<<<dim3((int)((size_t)NT * HFd / 256), NF), 256>>>(F_CAF, F_CBF, (size_t)NT * HFd, 0, HFd);
    act_kernel<<<dim3((int)((size_t)NT * HSd / 256), 4), 256>>>(F_CAS, F_CBS, (size_t)NT * HSd, 4, HSd);

    // fractal down (bf16)
    gemm_mma<1><<<dim3(DD / 256, NT / 128, NF), 512, SMEM_DYN>>>(
        F_CAF, (size_t)NT * HFd,
        frac_w2, frac_w2, (size_t)DD * HFd,
        F_Y, F_Y, (size_t)NT * DD,
        0, HFd, DD, 0);
    // switch down (x3 split)
    gemm_mma<3><<<dim3(DD / 256, NT / 128, 4), 512, SMEM_DYN>>>(
        F_CAS, (size_t)NT * HSd,
        sw_w2, sw_w2, (size_t)DD * HSd,
        F_Y + 4ull * NT * DD, F_Y + 4ull * NT * DD, (size_t)NT * DD,
        4, HSd, DD, 0);

    scatter_frac<<<dim3((NT * DD) / 256, NF), 256>>>(x, frac_gamma, out);
    scatter_sw<<<dim3((NT * DD) / 256, 4), 256>>>(out);
}

// round 5
// speedup vs baseline: 3.3242x; 1.2618x over previous
#include <cuda_runtime.h>
#include <cuda_bf16.h>
#include <cstdint>
#include <math.h>

#define NT  4096
#define DD  1024
#define HFd 2048
#define HSd 4096
#define NE  8
#define NF  4

// ---------------- routing state ----------------
__device__ int   g_cnt[NE];
__device__ int   g_idx[NE][NT];
__device__ float g_wt[NE][NT];

// ---------------- scratch layout (bytes) ----------------
constexpr size_t B_XGH = 0;                                   // [NE][NT][DD] bf16 hi
constexpr size_t B_XGL = B_XGH + (size_t)NE * NT * DD * 2;    // bf16 lo
constexpr size_t B_WF1H = B_XGL + (size_t)NE * NT * DD * 2;   // frac weights hi only
constexpr size_t SZ_WF = (size_t)NF * HFd * DD * 2;
constexpr size_t B_WF3H = B_WF1H + SZ_WF;
constexpr size_t B_WF2H = B_WF3H + SZ_WF;
constexpr size_t SZ_WS = (size_t)4 * HSd * DD * 2;
constexpr size_t B_WS1H = B_WF2H + SZ_WF;
constexpr size_t B_WS1L = B_WS1H + SZ_WS;
constexpr size_t B_WS3H = B_WS1L + SZ_WS;
constexpr size_t B_WS3L = B_WS3H + SZ_WS;
constexpr size_t B_WS2H = B_WS3L + SZ_WS;
constexpr size_t B_WS2L = B_WS2H + SZ_WS;
constexpr size_t B_HFH  = B_WS2L + SZ_WS;                     // frac act hi only
constexpr size_t B_HSH  = B_HFH + (size_t)NF * NT * HFd * 2;  // switch act hi/lo
constexpr size_t B_HSL  = B_HSH + (size_t)4 * NT * HSd * 2;
constexpr size_t B_CAF  = B_HSL + (size_t)4 * NT * HSd * 2;   // fp32 C buffers
constexpr size_t B_CBF  = B_CAF + (size_t)NF * NT * HFd * 4;
constexpr size_t B_CAS  = B_CBF + (size_t)NF * NT * HFd * 4;
constexpr size_t B_CBS  = B_CAS + (size_t)4 * NT * HSd * 4;
constexpr size_t B_Y    = B_CBS + (size_t)4 * NT * HSd * 4;   // fp32
constexpr size_t SCRATCH_BYTES = B_Y + (size_t)NE * NT * DD * 4;
__device__ __align__(1024) unsigned char g_scratch[SCRATCH_BYTES];

// ---------------- PTX helpers ----------------
__device__ __forceinline__ uint32_t smem_u32(const void* p) {
    uint32_t a;
    asm("{ .reg .u64 t; cvta.to.shared.u64 t, %1; cvt.u32.u64 %0, t; }" : "=r"(a) : "l"(p));
    return a;
}
__device__ __forceinline__ uint64_t gbl_u64(const void* p) {
    uint64_t a;
    asm("cvta.to.global.u64 %0, %1;" : "=l"(a) : "l"(p));
    return a;
}
__device__ __forceinline__ void cpa16(uint32_t s, uint64_t g) {
    asm volatile("cp.async.cg.shared.global [%0], [%1], 16;" :: "r"(s), "l"(g) : "memory");
}
__device__ __forceinline__ void cpa_commit() {
    asm volatile("cp.async.commit_group;" ::: "memory");
}
template<int N>
__device__ __forceinline__ void cpa_wait() {
    asm volatile("cp.async.wait_group %0;" :: "n"(N) : "memory");
}
__device__ __forceinline__ void ldm4(uint32_t* r, uint32_t addr) {
    asm volatile("ldmatrix.sync.aligned.m8n8.x4.shared.b16 {%0,%1,%2,%3}, [%4];"
        : "=r"(r[0]), "=r"(r[1]), "=r"(r[2]), "=r"(r[3]) : "r"(addr));
}
__device__ __forceinline__ void mma16816(float* d, const uint32_t* a, uint32_t b0, uint32_t b1) {
    asm volatile("mma.sync.aligned.m16n8k16.row.col.f32.bf16.bf16.f32 "
        "{%0,%1,%2,%3}, {%4,%5,%6,%7}, {%8,%9}, {%0,%1,%2,%3};"
        : "+f"(d[0]), "+f"(d[1]), "+f"(d[2]), "+f"(d[3])
        : "r"(a[0]), "r"(a[1]), "r"(a[2]), "r"(a[3]), "r"(b0), "r"(b1));
}
__device__ __forceinline__ uint32_t pack_bf2(float x, float y) {
    union { __nv_bfloat162 h; uint32_t u; } c;
    c.h = __float22bfloat162_rn(make_float2(x, y));
    return c.u;
}

// ---------------- reset ----------------
__global__ void reset_kernel(float* __restrict__ out) {
    size_t i = (size_t)blockIdx.x * 256u + threadIdx.x;
    out[i] = 0.f;
    if (i < NE) g_cnt[i] = 0;
}

// ---------------- router ----------------
__global__ void router_kernel(const float* __restrict__ x, const float* __restrict__ rw) {
    int gw = (int)((blockIdx.x * blockDim.x + threadIdx.x) >> 5);
    int lane = threadIdx.x & 31;
    if (gw >= NT) return;
    const float* xr = x + (size_t)gw * DD;
    float l[NE];
#pragma unroll
    for (int e = 0; e < NE; e++) {
        const float* wr = rw + (size_t)e * DD;
        float s = 0.f;
        for (int d = lane; d < DD; d += 32) s = fmaf(xr[d], wr[d], s);
#pragma unroll
        for (int o = 16; o; o >>= 1) s += __shfl_xor_sync(0xffffffffu, s, o);
        l[e] = s;
    }
    if (lane == 0) {
        float m = l[0];
#pragma unroll
        for (int e = 1; e < NE; e++) m = fmaxf(m, l[e]);
        float w[NE], sum = 0.f;
#pragma unroll
        for (int e = 0; e < NE; e++) { w[e] = expf(l[e] - m); sum += w[e]; }
        float inv = 1.f / sum;
#pragma unroll
        for (int e = 0; e < NE; e++) w[e] *= inv;
        int i1 = 0;
#pragma unroll
        for (int e = 1; e < NE; e++) if (w[e] > w[i1]) i1 = e;
        int i2 = (i1 == 0) ? 1 : 0;
#pragma unroll
        for (int e = 0; e < NE; e++) if (e != i1 && w[e] > w[i2]) i2 = e;
        float tw = fmaxf(w[i1] + w[i2], 1e-9f);
        int p1 = atomicAdd(&g_cnt[i1], 1);
        g_idx[i1][p1] = gw; g_wt[i1][p1] = w[i1] / tw;
        int p2 = atomicAdd(&g_cnt[i2], 1);
        g_idx[i2][p2] = gw; g_wt[i2][p2] = w[i2] / tw;
    }
}

// ---------------- gather: RMSNorm / copy -> bf16 hi/lo planes ----------------
__global__ void gather_kernel(const float* __restrict__ x, const float* __restrict__ frms) {
    int e = blockIdx.y;
    int s = blockIdx.x;
    if (s >= g_cnt[e]) return;
    int t = g_idx[e][s];
    int tid = threadIdx.x;
    float4 v = ((const float4*)(x + (size_t)t * DD))[tid];
    float o0 = v.x, o1 = v.y, o2 = v.z, o3 = v.w;
    if (e < NF) {
        float ss = v.x * v.x + v.y * v.y + v.z * v.z + v.w * v.w;
#pragma unroll
        for (int o = 16; o; o >>= 1) ss += __shfl_xor_sync(0xffffffffu, ss, o);
        __shared__ float red[8];
        if ((tid & 31) == 0) red[tid >> 5] = ss;
        __syncthreads();
        if (tid < 8) {
            float r = red[tid];
#pragma unroll
            for (int o = 4; o; o >>= 1) r += __shfl_xor_sync(0x000000ffu, r, o);
            if (tid == 0) red[0] = r;
        }
        __syncthreads();
        float scale = rsqrtf(red[0] * (1.f / DD) + 1e-6f);
        float4 g = ((const float4*)(frms + (size_t)e * DD))[tid];
        o0 = v.x * scale * g.x; o1 = v.y * scale * g.y;
        o2 = v.z * scale * g.z; o3 = v.w * scale * g.w;
    }
    size_t base = ((size_t)e * NT + s) * DD + (size_t)tid * 4;
    uint32_t h0 = pack_bf2(o0, o1), h1 = pack_bf2(o2, o3);
    float hf0 = __bfloat162float(__ushort_as_bfloat16((unsigned short)(h0 & 0xffff)));
    float hf1 = __bfloat162float(__ushort_as_bfloat16((unsigned short)(h0 >> 16)));
    float hf2 = __bfloat162float(__ushort_as_bfloat16((unsigned short)(h1 & 0xffff)));
    float hf3 = __bfloat162float(__ushort_as_bfloat16((unsigned short)(h1 >> 16)));
    uint32_t l0 = pack_bf2(o0 - hf0, o1 - hf1), l1 = pack_bf2(o2 - hf2, o3 - hf3);
    *(uint2*)((__nv_bfloat16*)(g_scratch + B_XGH) + base) = make_uint2(h0, h1);
    *(uint2*)((__nv_bfloat16*)(g_scratch + B_XGL) + base) = make_uint2(l0, l1);
}

// ---------------- weight fp32 -> bf16 hi (+lo) ----------------
__global__ void conv_split(const float* __restrict__ src, size_t offH, size_t offL, int hasLo) {
    size_t i = ((size_t)blockIdx.x * 256u + threadIdx.x) * 8;
    float4 v0 = *(const float4*)(src + i);
    float4 v1 = *(const float4*)(src + i + 4);
    float v[8] = {v0.x, v0.y, v0.z, v0.w, v1.x, v1.y, v1.z, v1.w};
    uint32_t H[4], L[4];
#pragma unroll
    for (int j = 0; j < 4; j++) {
        H[j] = pack_bf2(v[2 * j], v[2 * j + 1]);
        float a = __bfloat162float(__ushort_as_bfloat16((unsigned short)(H[j] & 0xffff)));
        float b = __bfloat162float(__ushort_as_bfloat16((unsigned short)(H[j] >> 16)));
        L[j] = pack_bf2(v[2 * j] - a, v[2 * j + 1] - b);
    }
    *(uint4*)((__nv_bfloat16*)(g_scratch + offH) + i) = make_uint4(H[0], H[1], H[2], H[3]);
    if (hasLo)
        *(uint4*)((__nv_bfloat16*)(g_scratch + offL) + i) = make_uint4(L[0], L[1], L[2], L[3]);
}

// ---------------- cp.async multi-stage tensor-core GEMM ----------------
// C[m,n] = sum_k A[m,k]*B[n,k]; A,B pre-split bf16 planes in g_scratch.
// CTA tile 128x256, 16 warps (4x4), warp tile 32x64, k-chunk 32.
#define SROW    80
#define APLANE  10240u
#define BPLANE  20480u

template<int NSPLIT>
__global__ void __launch_bounds__(512, 1)
gemm_cp(size_t oAh, size_t oAl, size_t strideA,
        size_t oBh0, size_t oBl0, size_t oBh1, size_t oBl1, size_t strideB,
        size_t oC0, size_t oC1, size_t strideC,
        int cntBase, int K, int Nn, int dualB)
{
    constexpr int STAGES = (NSPLIT == 3) ? 3 : 5;
    constexpr uint32_t OFFB = (NSPLIT == 3) ? 2 * APLANE : APLANE;
    constexpr uint32_t STG = (NSPLIT == 3) ? (2 * APLANE + 2 * BPLANE) : (APLANE + BPLANE);

    const int z = blockIdx.z;
    const int e = dualB ? (z >> 1) : z;
    const int which = dualB ? (z & 1) : 0;
    const int cnt = g_cnt[cntBase + e];
    const int m0 = blockIdx.y * 128;
    if (m0 >= cnt) return;
    const int n0 = blockIdx.x * 256;

    const __nv_bfloat16* Ahi = (const __nv_bfloat16*)(g_scratch + oAh) + (size_t)e * strideA;
    const __nv_bfloat16* Alo = (const __nv_bfloat16*)(g_scratch + oAl) + (size_t)e * strideA;
    const __nv_bfloat16* Bhi = (const __nv_bfloat16*)(g_scratch + (which ? oBh1 : oBh0)) + (size_t)e * strideB;
    const __nv_bfloat16* Blo = (const __nv_bfloat16*)(g_scratch + (which ? oBl1 : oBl0)) + (size_t)e * strideB;
    float* C = (float*)(g_scratch + (which ? oC1 : oC0)) + (size_t)e * strideC;

    extern __shared__ char smem[];
    const uint32_t sb = smem_u32(smem);

    const int tid  = threadIdx.x;
    const int lane = tid & 31;
    const int wid  = tid >> 5;
    const int mr   = wid & 3;
    const int nc   = wid >> 2;

    // cp.async per-thread source/dest
    const int row = tid >> 2;
    const int grp = tid & 3;
    const uint64_t gAh = gbl_u64(Ahi + (size_t)(m0 + row) * K + grp * 8);
    const uint64_t gAl = gbl_u64(Alo + (size_t)(m0 + row) * K + grp * 8);
    const uint64_t gB0h = gbl_u64(Bhi + (size_t)(n0 + row) * K + grp * 8);
    const uint64_t gB1h = gbl_u64(Bhi + (size_t)(n0 + 128 + row) * K + grp * 8);
    const uint64_t gB0l = gbl_u64(Blo + (size_t)(n0 + row) * K + grp * 8);
    const uint64_t gB1l = gbl_u64(Blo + (size_t)(n0 + 128 + row) * K + grp * 8);
    const uint32_t sA  = (uint32_t)row * SROW + grp * 16;
    const uint32_t sB0 = OFFB + (uint32_t)row * SROW + grp * 16;
    const uint32_t sB1 = sB0 + 128u * SROW;

    // ldmatrix lane addresses
    const uint32_t aL = (uint32_t)(mr * 32 + (lane & 15)) * SROW + ((lane >> 4) * 16);
    const int bnoff = (lane & 7) + ((lane >> 4) << 3);
    const uint32_t bL = OFFB + (uint32_t)(nc * 64 + bnoff) * SROW + (((lane >> 3) & 1) * 16);

    float acc[2][8][4];
#pragma unroll
    for (int i = 0; i < 2; i++)
#pragma unroll
        for (int j = 0; j < 8; j++)
#pragma unroll
            for (int q = 0; q < 4; q++) acc[i][j][q] = 0.f;

    const int nst = K >> 5;

    auto issue = [&](int kc, uint32_t base) {
        uint64_t d = (uint64_t)kc * 64;  // 32 elems * 2B
        cpa16(base + sA, gAh + d);
        cpa16(base + sB0, gB0h + d);
        cpa16(base + sB1, gB1h + d);
        if (NSPLIT == 3) {
            cpa16(base + sA + APLANE, gAl + d);
            cpa16(base + sB0 + BPLANE, gB0l + d);
            cpa16(base + sB1 + BPLANE, gB1l + d);
        }
    };

#pragma unroll
    for (int s = 0; s < STAGES - 1; s++) {
        issue(s, sb + (uint32_t)s * STG);
        cpa_commit();
    }

    int slot = 0, wslot = STAGES - 1;
    for (int kc = 0; kc < nst; kc++) {
        cpa_wait<STAGES - 2>();
        __syncthreads();
        const int knext = kc + STAGES - 1;
        if (knext < nst) issue(knext, sb + (uint32_t)wslot * STG);
        cpa_commit();

        const uint32_t base = sb + (uint32_t)slot * STG;
#pragma unroll
        for (int k16 = 0; k16 < 2; k16++) {
            uint32_t ah[2][4], al[2][4];
#pragma unroll
            for (int mt = 0; mt < 2; mt++) {
                ldm4(ah[mt], base + aL + (uint32_t)(mt * 16) * SROW + k16 * 32);
                if (NSPLIT == 3)
                    ldm4(al[mt], base + aL + APLANE + (uint32_t)(mt * 16) * SROW + k16 * 32);
            }
#pragma unroll
            for (int np = 0; np < 4; np++) {
                uint32_t bh[4], bl[4];
                ldm4(bh, base + bL + (uint32_t)(np * 16) * SROW + k16 * 32);
                if (NSPLIT == 3)
                    ldm4(bl, base + bL + BPLANE + (uint32_t)(np * 16) * SROW + k16 * 32);
#pragma unroll
                for (int mt = 0; mt < 2; mt++)
#pragma unroll
                    for (int s2 = 0; s2 < 2; s2++) {
                        float* d = acc[mt][np * 2 + s2];
                        mma16816(d, ah[mt], bh[2 * s2], bh[2 * s2 + 1]);
                        if (NSPLIT == 3) {
                            mma16816(d, ah[mt], bl[2 * s2], bl[2 * s2 + 1]);
                            mma16816(d, al[mt], bh[2 * s2], bh[2 * s2 + 1]);
                        }
                    }
            }
        }
        slot = (slot + 1 < STAGES) ? slot + 1 : 0;
        wslot = (wslot + 1 < STAGES) ? wslot + 1 : 0;
    }

    // epilogue
#pragma unroll
    for (int mt = 0; mt < 2; mt++) {
        int r0 = m0 + mr * 32 + mt * 16 + (lane >> 2);
#pragma unroll
        for (int j = 0; j < 8; j++) {
            int col = n0 + nc * 64 + j * 8 + 2 * (lane & 3);
            if (r0 < cnt)
                *(float2*)(C + (size_t)r0 * Nn + col) = make_float2(acc[mt][j][0], acc[mt][j][1]);
            if (r0 + 8 < cnt)
                *(float2*)(C + (size_t)(r0 + 8) * Nn + col) = make_float2(acc[mt][j][2], acc[mt][j][3]);
        }
    }
}

// ---------------- silu(a)*b -> bf16 hi (+lo) planes ----------------
__global__ void act_kernel(size_t offCA, size_t offCB, size_t offHh, size_t offHl,
                           size_t stride, int cntBase, int H, int hasLo) {
    int z = blockIdx.y;
    size_t i = ((size_t)blockIdx.x * 256u + threadIdx.x) * 4;
    if (i >= (size_t)g_cnt[cntBase + z] * H) return;
    const float* Aq = (const float*)(g_scratch + offCA) + (size_t)z * stride;
    const float* Bq = (const float*)(g_scratch + offCB) + (size_t)z * stride;
    float4 a = *(const float4*)(Aq + i);
    float4 b = *(const float4*)(Bq + i);
    float h[4];
    h[0] = (a.x / (1.f + expf(-a.x))) * b.x;
    h[1] = (a.y / (1.f + expf(-a.y))) * b.y;
    h[2] = (a.z / (1.f + expf(-a.z))) * b.z;
    h[3] = (a.w / (1.f + expf(-a.w))) * b.w;
    uint32_t h0 = pack_bf2(h[0], h[1]), h1 = pack_bf2(h[2], h[3]);
    *(uint2*)((__nv_bfloat16*)(g_scratch + offHh) + (size_t)z * stride + i) = make_uint2(h0, h1);
    if (hasLo) {
        float f0 = __bfloat162float(__ushort_as_bfloat16((unsigned short)(h0 & 0xffff)));
        float f1 = __bfloat162float(__ushort_as_bfloat16((unsigned short)(h0 >> 16)));
        float f2 = __bfloat162float(__ushort_as_bfloat16((unsigned short)(h1 & 0xffff)));
        float f3 = __bfloat162float(__ushort_as_bfloat16((unsigned short)(h1 >> 16)));
        uint32_t l0 = pack_bf2(h[0] - f0, h[1] - f1), l1 = pack_bf2(h[2] - f2, h[3] - f3);
        *(uint2*)((__nv_bfloat16*)(g_scratch + offHl) + (size_t)z * stride + i) = make_uint2(l0, l1);
    }
}

// ---------------- scatter epilogues ----------------
__global__ void scatter_frac(const float* __restrict__ x, const float* __restrict__ gamma,
                             float* __restrict__ out) {
    int e = blockIdx.y;
    size_t i = (size_t)blockIdx.x * 256u + threadIdx.x;
    int s = (int)(i / DD);
    if (s >= g_cnt[e]) return;
    int d = (int)(i % DD);
    int t = g_idx[e][s];
    float w = g_wt[e][s];
    size_t base = (size_t)e * NT * DD + i;
    float xn = __bfloat162float(((const __nv_bfloat16*)(g_scratch + B_XGH))[base])
             + __bfloat162float(((const __nv_bfloat16*)(g_scratch + B_XGL))[base]);
    float y = ((const float*)(g_scratch + B_Y))[base];
    float val = gamma[(size_t)e * DD + d] * (xn + y) + x[(size_t)t * DD + d];
    atomicAdd(&out[(size_t)t * DD + d], w * val);
}

__global__ void scatter_sw(float* __restrict__ out) {
    int j = blockIdx.y;
    int e = NF + j;
    size_t i = (size_t)blockIdx.x * 256u + threadIdx.x;
    int s = (int)(i / DD);
    if (s >= g_cnt[e]) return;
    int t = g_idx[e][s];
    float w = g_wt[e][s];
    float y = ((const float*)(g_scratch + B_Y))[(size_t)e * NT * DD + i];
    atomicAdd(&out[(size_t)t * DD + (i % DD)], w * y);
}

// ---------------- launch ----------------
extern "C" void kernel_launch(void* const* d_in, const int* in_sizes, int n_in,
                              void* d_out, int out_size) {
    const float* x          = (const float*)d_in[0];
    const float* router_w   = (const float*)d_in[1];
    const float* frac_rms   = (const float*)d_in[2];
    const float* frac_w1    = (const float*)d_in[3];
    const float* frac_w2    = (const float*)d_in[4];
    const float* frac_w3    = (const float*)d_in[5];
    const float* frac_gamma = (const float*)d_in[6];
    const float* sw_w1      = (const float*)d_in[7];
    const float* sw_w2      = (const float*)d_in[8];
    const float* sw_w3      = (const float*)d_in[9];
    float* out = (float*)d_out;
    (void)in_sizes; (void)n_in; (void)out_size;

    constexpr int SM3 = 3 * (2 * 10240 + 2 * 20480);  // 184320
    constexpr int SM1 = 5 * (10240 + 20480);          // 153600
    cudaFuncSetAttribute(gemm_cp<3>, cudaFuncAttributeMaxDynamicSharedMemorySize, SM3);
    cudaFuncSetAttribute(gemm_cp<1>, cudaFuncAttributeMaxDynamicSharedMemorySize, SM1);

    reset_kernel<<<(NT * DD) / 256, 256>>>(out);
    router_kernel<<<NT / 8, 256>>>(x, router_w);
    gather_kernel<<<dim3(NT, NE), 256>>>(x, frac_rms);

    // weight conversions (fractal hi-only; switch hi+lo)
    conv_split<<<(int)(SZ_WF / 2 / 2048), 256>>>(frac_w1, B_WF1H, 0, 0);
    conv_split<<<(int)(SZ_WF / 2 / 2048), 256>>>(frac_w3, B_WF3H, 0, 0);
    conv_split<<<(int)(SZ_WF / 2 / 2048), 256>>>(frac_w2, B_WF2H, 0, 0);
    conv_split<<<(int)(SZ_WS / 2 / 2048), 256>>>(sw_w1, B_WS1H, B_WS1L, 1);
    conv_split<<<(int)(SZ_WS / 2 / 2048), 256>>>(sw_w3, B_WS3H, B_WS3L, 1);
    conv_split<<<(int)(SZ_WS / 2 / 2048), 256>>>(sw_w2, B_WS2H, B_WS2L, 1);

    // fractal up (bf16, dualB): xn @ w1^T / w3^T
    gemm_cp<1><<<dim3(HFd / 256, NT / 128, 2 * NF), 512, SM1>>>(
        B_XGH, B_XGL, (size_t)NT * DD,
        B_WF1H, 0, B_WF3H, 0, (size_t)HFd * DD,
        B_CAF, B_CBF, (size_t)NT * HFd,
        0, DD, HFd, 1);
    // switch up (x3 split, dualB)
    gemm_cp<3><<<dim3(HSd / 256, NT / 128, 8), 512, SM3>>>(
        B_XGH + (size_t)4 * NT * DD * 2, B_XGL + (size_t)4 * NT * DD * 2, (size_t)NT * DD,
        B_WS1H, B_WS1L, B_WS3H, B_WS3L, (size_t)HSd * DD,
        B_CAS, B_CBS, (size_t)NT * HSd,
        4, DD, HSd, 1);

    // silu * gate -> bf16 planes
    act_kernel<<<dim3((int)((size_t)NT * HFd / 1024), NF), 256>>>(
        B_CAF, B_CBF, B_HFH, 0, (size_t)NT * HFd, 0, HFd, 0);
    act_kernel<<<dim3((int)((size_t)NT * HSd / 1024), 4), 256>>>(
        B_CAS, B_CBS, B_HSH, B_HSL, (size_t)NT * HSd, 4, HSd, 1);

    // fractal down (bf16)
    gemm_cp<1><<<dim3(DD / 256, NT / 128, NF), 512, SM1>>>(
        B_HFH, B_HFH, (size_t)NT * HFd,
        B_WF2H, 0, B_WF2H, 0, (size_t)DD * HFd,
        B_Y, B_Y, (size_t)NT * DD,
        0, HFd, DD, 0);
    // switch down (x3 split)
    gemm_cp<3><<<dim3(DD / 256, NT / 128, 4), 512, SM3>>>(
        B_HSH, B_HSL, (size_t)NT * HSd,
        B_WS2H, B_WS2L, B_WS2H, B_WS2L, (size_t)DD * HSd,
        B_Y + (size_t)4 * NT * DD * 4, B_Y + (size_t)4 * NT * DD * 4, (size_t)NT * DD,
        4, HSd, DD, 0);

    scatter_frac<<<dim3((NT * DD) / 256, NF), 256>>>(x, frac_gamma, out);
    scatter_sw<<<dim3((NT * DD) / 256, 4), 256>>>(out);
}

// round 6
// speedup vs baseline: 3.4340x; 1.0330x over previous
#include <cuda_runtime.h>
#include <cuda_bf16.h>
#include <cstdint>
#include <math.h>

#define NT  4096
#define DD  1024
#define HFd 2048
#define HSd 4096
#define NE  8
#define NF  4

// ---------------- routing state ----------------
__device__ int   g_cnt[NE];
__device__ int   g_idx[NE][NT];       // slot -> token
__device__ int   g_te[NT][2];         // token -> expert
__device__ int   g_ts[NT][2];         // token -> slot
__device__ float g_tw[NT][2];         // token -> weight

// ---------------- scratch layout (bytes) ----------------
constexpr size_t B_XGH = 0;                                   // [NE][NT][DD] bf16 hi
constexpr size_t B_XGL = B_XGH + (size_t)NE * NT * DD * 2;    // bf16 lo
constexpr size_t B_WF1H = B_XGL + (size_t)NE * NT * DD * 2;   // frac weights hi only
constexpr size_t SZ_WF = (size_t)NF * HFd * DD * 2;
constexpr size_t B_WF3H = B_WF1H + SZ_WF;
constexpr size_t B_WF2H = B_WF3H + SZ_WF;
constexpr size_t SZ_WS = (size_t)4 * HSd * DD * 2;
constexpr size_t B_WS1H = B_WF2H + SZ_WF;
constexpr size_t B_WS1L = B_WS1H + SZ_WS;
constexpr size_t B_WS3H = B_WS1L + SZ_WS;
constexpr size_t B_WS3L = B_WS3H + SZ_WS;
constexpr size_t B_WS2H = B_WS3L + SZ_WS;
constexpr size_t B_WS2L = B_WS2H + SZ_WS;
constexpr size_t B_HFH  = B_WS2L + SZ_WS;                     // frac act hi only
constexpr size_t B_HSH  = B_HFH + (size_t)NF * NT * HFd * 2;  // switch act hi/lo
constexpr size_t B_HSL  = B_HSH + (size_t)4 * NT * HSd * 2;
constexpr size_t B_CAF  = B_HSL + (size_t)4 * NT * HSd * 2;   // fp32 gate buffers
constexpr size_t B_CAS  = B_CAF + (size_t)NF * NT * HFd * 4;
constexpr size_t B_Y    = B_CAS + (size_t)4 * NT * HSd * 4;   // fp32 down-proj out
constexpr size_t SCRATCH_BYTES = B_Y + (size_t)NE * NT * DD * 4;
__device__ __align__(1024) unsigned char g_scratch[SCRATCH_BYTES];

// ---------------- PTX helpers ----------------
__device__ __forceinline__ uint32_t smem_u32(const void* p) {
    uint32_t a;
    asm("{ .reg .u64 t; cvta.to.shared.u64 t, %1; cvt.u32.u64 %0, t; }" : "=r"(a) : "l"(p));
    return a;
}
__device__ __forceinline__ uint64_t gbl_u64(const void* p) {
    uint64_t a;
    asm("cvta.to.global.u64 %0, %1;" : "=l"(a) : "l"(p));
    return a;
}
__device__ __forceinline__ void cpa16(uint32_t s, uint64_t g) {
    asm volatile("cp.async.cg.shared.global [%0], [%1], 16;" :: "r"(s), "l"(g) : "memory");
}
__device__ __forceinline__ void cpa_commit() {
    asm volatile("cp.async.commit_group;" ::: "memory");
}
template<int N>
__device__ __forceinline__ void cpa_wait() {
    asm volatile("cp.async.wait_group %0;" :: "n"(N) : "memory");
}
__device__ __forceinline__ void ldm4(uint32_t* r, uint32_t addr) {
    asm volatile("ldmatrix.sync.aligned.m8n8.x4.shared.b16 {%0,%1,%2,%3}, [%4];"
        : "=r"(r[0]), "=r"(r[1]), "=r"(r[2]), "=r"(r[3]) : "r"(addr));
}
__device__ __forceinline__ void mma16816(float* d, const uint32_t* a, uint32_t b0, uint32_t b1) {
    asm volatile("mma.sync.aligned.m16n8k16.row.col.f32.bf16.bf16.f32 "
        "{%0,%1,%2,%3}, {%4,%5,%6,%7}, {%8,%9}, {%0,%1,%2,%3};"
        : "+f"(d[0]), "+f"(d[1]), "+f"(d[2]), "+f"(d[3])
        : "r"(a[0]), "r"(a[1]), "r"(a[2]), "r"(a[3]), "r"(b0), "r"(b1));
}
__device__ __forceinline__ uint32_t pack_bf2(float x, float y) {
    union { __nv_bfloat162 h; uint32_t u; } c;
    c.h = __float22bfloat162_rn(make_float2(x, y));
    return c.u;
}
__device__ __forceinline__ float2 unpack_bf2(uint32_t u) {
    union { uint32_t v; __nv_bfloat162 h; } c; c.v = u;
    return __bfloat1622float2(c.h);
}
__device__ __forceinline__ float silu(float a) { return a / (1.f + expf(-a)); }

// ---------------- reset counts ----------------
__global__ void reset_cnt() {
    if (threadIdx.x < NE) g_cnt[threadIdx.x] = 0;
}

// ---------------- router ----------------
__global__ void router_kernel(const float* __restrict__ x, const float* __restrict__ rw) {
    int gw = (int)((blockIdx.x * blockDim.x + threadIdx.x) >> 5);
    int lane = threadIdx.x & 31;
    if (gw >= NT) return;
    const float* xr = x + (size_t)gw * DD;
    float l[NE];
#pragma unroll
    for (int e = 0; e < NE; e++) {
        const float* wr = rw + (size_t)e * DD;
        float s = 0.f;
        for (int d = lane; d < DD; d += 32) s = fmaf(xr[d], wr[d], s);
#pragma unroll
        for (int o = 16; o; o >>= 1) s += __shfl_xor_sync(0xffffffffu, s, o);
        l[e] = s;
    }
    if (lane == 0) {
        float m = l[0];
#pragma unroll
        for (int e = 1; e < NE; e++) m = fmaxf(m, l[e]);
        float w[NE], sum = 0.f;
#pragma unroll
        for (int e = 0; e < NE; e++) { w[e] = expf(l[e] - m); sum += w[e]; }
        float inv = 1.f / sum;
#pragma unroll
        for (int e = 0; e < NE; e++) w[e] *= inv;
        int i1 = 0;
#pragma unroll
        for (int e = 1; e < NE; e++) if (w[e] > w[i1]) i1 = e;
        int i2 = (i1 == 0) ? 1 : 0;
#pragma unroll
        for (int e = 0; e < NE; e++) if (e != i1 && w[e] > w[i2]) i2 = e;
        float tw = fmaxf(w[i1] + w[i2], 1e-9f);
        int p1 = atomicAdd(&g_cnt[i1], 1);
        g_idx[i1][p1] = gw;
        int p2 = atomicAdd(&g_cnt[i2], 1);
        g_idx[i2][p2] = gw;
        g_te[gw][0] = i1; g_ts[gw][0] = p1; g_tw[gw][0] = w[i1] / tw;
        g_te[gw][1] = i2; g_ts[gw][1] = p2; g_tw[gw][1] = w[i2] / tw;
    }
}

// ---------------- gather: RMSNorm / copy -> bf16 hi/lo planes ----------------
__global__ void gather_kernel(const float* __restrict__ x, const float* __restrict__ frms) {
    int e = blockIdx.y;
    int s = blockIdx.x;
    if (s >= g_cnt[e]) return;
    int t = g_idx[e][s];
    int tid = threadIdx.x;
    float4 v = ((const float4*)(x + (size_t)t * DD))[tid];
    float o0 = v.x, o1 = v.y, o2 = v.z, o3 = v.w;
    if (e < NF) {
        float ss = v.x * v.x + v.y * v.y + v.z * v.z + v.w * v.w;
#pragma unroll
        for (int o = 16; o; o >>= 1) ss += __shfl_xor_sync(0xffffffffu, ss, o);
        __shared__ float red[8];
        if ((tid & 31) == 0) red[tid >> 5] = ss;
        __syncthreads();
        if (tid < 8) {
            float r = red[tid];
#pragma unroll
            for (int o = 4; o; o >>= 1) r += __shfl_xor_sync(0x000000ffu, r, o);
            if (tid == 0) red[0] = r;
        }
        __syncthreads();
        float scale = rsqrtf(red[0] * (1.f / DD) + 1e-6f);
        float4 g = ((const float4*)(frms + (size_t)e * DD))[tid];
        o0 = v.x * scale * g.x; o1 = v.y * scale * g.y;
        o2 = v.z * scale * g.z; o3 = v.w * scale * g.w;
    }
    size_t base = ((size_t)e * NT + s) * DD + (size_t)tid * 4;
    uint32_t h0 = pack_bf2(o0, o1), h1 = pack_bf2(o2, o3);
    float2 f0 = unpack_bf2(h0), f1 = unpack_bf2(h1);
    uint32_t l0 = pack_bf2(o0 - f0.x, o1 - f0.y), l1 = pack_bf2(o2 - f1.x, o3 - f1.y);
    *(uint2*)((__nv_bfloat16*)(g_scratch + B_XGH) + base) = make_uint2(h0, h1);
    *(uint2*)((__nv_bfloat16*)(g_scratch + B_XGL) + base) = make_uint2(l0, l1);
}

// ---------------- weight fp32 -> bf16 conversions (merged) ----------------
__global__ void conv_frac(const float* __restrict__ w1, const float* __restrict__ w3,
                          const float* __restrict__ w2) {
    int z = blockIdx.y;
    const float* src = (z == 0) ? w1 : (z == 1) ? w3 : w2;
    size_t offH = (z == 0) ? B_WF1H : (z == 1) ? B_WF3H : B_WF2H;
    size_t i = ((size_t)blockIdx.x * 256u + threadIdx.x) * 8;
    float4 v0 = *(const float4*)(src + i);
    float4 v1 = *(const float4*)(src + i + 4);
    uint4 H = make_uint4(pack_bf2(v0.x, v0.y), pack_bf2(v0.z, v0.w),
                         pack_bf2(v1.x, v1.y), pack_bf2(v1.z, v1.w));
    *(uint4*)((__nv_bfloat16*)(g_scratch + offH) + i) = H;
}
__global__ void conv_sw(const float* __restrict__ w1, const float* __restrict__ w3,
                        const float* __restrict__ w2) {
    int z = blockIdx.y;
    const float* src = (z == 0) ? w1 : (z == 1) ? w3 : w2;
    size_t offH = (z == 0) ? B_WS1H : (z == 1) ? B_WS3H : B_WS2H;
    size_t offL = (z == 0) ? B_WS1L : (z == 1) ? B_WS3L : B_WS2L;
    size_t i = ((size_t)blockIdx.x * 256u + threadIdx.x) * 8;
    float4 v0 = *(const float4*)(src + i);
    float4 v1 = *(const float4*)(src + i + 4);
    float v[8] = {v0.x, v0.y, v0.z, v0.w, v1.x, v1.y, v1.z, v1.w};
    uint32_t H[4], L[4];
#pragma unroll
    for (int j = 0; j < 4; j++) {
        H[j] = pack_bf2(v[2 * j], v[2 * j + 1]);
        float2 f = unpack_bf2(H[j]);
        L[j] = pack_bf2(v[2 * j] - f.x, v[2 * j + 1] - f.y);
    }
    *(uint4*)((__nv_bfloat16*)(g_scratch + offH) + i) = make_uint4(H[0], H[1], H[2], H[3]);
    *(uint4*)((__nv_bfloat16*)(g_scratch + offL) + i) = make_uint4(L[0], L[1], L[2], L[3]);
}

// ---------------- cp.async multi-stage tensor-core GEMM ----------------
// C[m,n] = sum_k A[m,k]*B[n,k]; A,B pre-split bf16 planes in g_scratch.
// CTA tile 128x256, 16 warps (4x4), warp tile 32x64, k-chunk 32.
// MODE 0: write fp32 C.  MODE 1: fused h = silu(gateC)*acc -> bf16 planes.
#define SROW    80
#define APLANE  10240u
#define BPLANE  20480u

template<int NSPLIT, int MODE>
__global__ void __launch_bounds__(512, 1)
gemm_cp(size_t oAh, size_t oAl, size_t strideA,
        size_t oBh, size_t oBl, size_t strideB,
        size_t oC, size_t oHh, size_t oHl, size_t strideC,
        int cntBase, int K, int Nn)
{
    constexpr int STAGES = (NSPLIT == 3) ? 3 : 5;
    constexpr uint32_t OFFB = (NSPLIT == 3) ? 2 * APLANE : APLANE;
    constexpr uint32_t STG = (NSPLIT == 3) ? (2 * APLANE + 2 * BPLANE) : (APLANE + BPLANE);

    const int e = blockIdx.z;
    const int cnt = g_cnt[cntBase + e];
    const int m0 = blockIdx.y * 128;
    if (m0 >= cnt) return;
    const int n0 = blockIdx.x * 256;

    const __nv_bfloat16* Ahi = (const __nv_bfloat16*)(g_scratch + oAh) + (size_t)e * strideA;
    const __nv_bfloat16* Alo = (const __nv_bfloat16*)(g_scratch + oAl) + (size_t)e * strideA;
    const __nv_bfloat16* Bhi = (const __nv_bfloat16*)(g_scratch + oBh) + (size_t)e * strideB;
    const __nv_bfloat16* Blo = (const __nv_bfloat16*)(g_scratch + oBl) + (size_t)e * strideB;

    extern __shared__ char smem[];
    const uint32_t sb = smem_u32(smem);

    const int tid  = threadIdx.x;
    const int lane = tid & 31;
    const int wid  = tid >> 5;
    const int mr   = wid & 3;
    const int nc   = wid >> 2;

    const int row = tid >> 2;
    const int grp = tid & 3;
    const uint64_t gAh = gbl_u64(Ahi + (size_t)(m0 + row) * K + grp * 8);
    const uint64_t gAl = gbl_u64(Alo + (size_t)(m0 + row) * K + grp * 8);
    const uint64_t gB0h = gbl_u64(Bhi + (size_t)(n0 + row) * K + grp * 8);
    const uint64_t gB1h = gbl_u64(Bhi + (size_t)(n0 + 128 + row) * K + grp * 8);
    const uint64_t gB0l = gbl_u64(Blo + (size_t)(n0 + row) * K + grp * 8);
    const uint64_t gB1l = gbl_u64(Blo + (size_t)(n0 + 128 + row) * K + grp * 8);
    const uint32_t sA  = (uint32_t)row * SROW + grp * 16;
    const uint32_t sB0 = OFFB + (uint32_t)row * SROW + grp * 16;
    const uint32_t sB1 = sB0 + 128u * SROW;

    const uint32_t aL = (uint32_t)(mr * 32 + (lane & 15)) * SROW + ((lane >> 4) * 16);
    const int bnoff = (lane & 7) + ((lane >> 4) << 3);
    const uint32_t bL = OFFB + (uint32_t)(nc * 64 + bnoff) * SROW + (((lane >> 3) & 1) * 16);

    float acc[2][8][4];
#pragma unroll
    for (int i = 0; i < 2; i++)
#pragma unroll
        for (int j = 0; j < 8; j++)
#pragma unroll
            for (int q = 0; q < 4; q++) acc[i][j][q] = 0.f;

    const int nst = K >> 5;

    auto issue = [&](int kc, uint32_t base) {
        uint64_t d = (uint64_t)kc * 64;
        cpa16(base + sA, gAh + d);
        cpa16(base + sB0, gB0h + d);
        cpa16(base + sB1, gB1h + d);
        if (NSPLIT == 3) {
            cpa16(base + sA + APLANE, gAl + d);
            cpa16(base + sB0 + BPLANE, gB0l + d);
            cpa16(base + sB1 + BPLANE, gB1l + d);
        }
    };

#pragma unroll
    for (int s = 0; s < STAGES - 1; s++) {
        issue(s, sb + (uint32_t)s * STG);
        cpa_commit();
    }

    int slot = 0, wslot = STAGES - 1;
    for (int kc = 0; kc < nst; kc++) {
        cpa_wait<STAGES - 2>();
        __syncthreads();
        const int knext = kc + STAGES - 1;
        if (knext < nst) issue(knext, sb + (uint32_t)wslot * STG);
        cpa_commit();

        const uint32_t base = sb + (uint32_t)slot * STG;
#pragma unroll
        for (int k16 = 0; k16 < 2; k16++) {
            uint32_t ah[2][4], al[2][4];
#pragma unroll
            for (int mt = 0; mt < 2; mt++) {
                ldm4(ah[mt], base + aL + (uint32_t)(mt * 16) * SROW + k16 * 32);
                if (NSPLIT == 3)
                    ldm4(al[mt], base + aL + APLANE + (uint32_t)(mt * 16) * SROW + k16 * 32);
            }
#pragma unroll
            for (int np = 0; np < 4; np++) {
                uint32_t bh[4], bl[4];
                ldm4(bh, base + bL + (uint32_t)(np * 16) * SROW + k16 * 32);
                if (NSPLIT == 3)
                    ldm4(bl, base + bL + BPLANE + (uint32_t)(np * 16) * SROW + k16 * 32);
#pragma unroll
                for (int mt = 0; mt < 2; mt++)
#pragma unroll
                    for (int s2 = 0; s2 < 2; s2++) {
                        float* d = acc[mt][np * 2 + s2];
                        mma16816(d, ah[mt], bh[2 * s2], bh[2 * s2 + 1]);
                        if (NSPLIT == 3) {
                            mma16816(d, ah[mt], bl[2 * s2], bl[2 * s2 + 1]);
                            mma16816(d, al[mt], bh[2 * s2], bh[2 * s2 + 1]);
                        }
                    }
            }
        }
        slot = (slot + 1 < STAGES) ? slot + 1 : 0;
        wslot = (wslot + 1 < STAGES) ? wslot + 1 : 0;
    }

    // ---------------- epilogue ----------------
    if (MODE == 0) {
        float* C = (float*)(g_scratch + oC) + (size_t)e * strideC;
#pragma unroll
        for (int mt = 0; mt < 2; mt++) {
            int r0 = m0 + mr * 32 + mt * 16 + (lane >> 2);
#pragma unroll
            for (int j = 0; j < 8; j++) {
                int col = n0 + nc * 64 + j * 8 + 2 * (lane & 3);
                if (r0 < cnt)
                    *(float2*)(C + (size_t)r0 * Nn + col) = make_float2(acc[mt][j][0], acc[mt][j][1]);
                if (r0 + 8 < cnt)
                    *(float2*)(C + (size_t)(r0 + 8) * Nn + col) = make_float2(acc[mt][j][2], acc[mt][j][3]);
            }
        }
    } else {
        const float* CA = (const float*)(g_scratch + oC) + (size_t)e * strideC;
        __nv_bfloat16* Hh = (__nv_bfloat16*)(g_scratch + oHh) + (size_t)e * strideC;
        __nv_bfloat16* Hl = (__nv_bfloat16*)(g_scratch + oHl) + (size_t)e * strideC;
#pragma unroll
        for (int mt = 0; mt < 2; mt++) {
            int r0 = m0 + mr * 32 + mt * 16 + (lane >> 2);
#pragma unroll
            for (int j = 0; j < 8; j++) {
                int col = n0 + nc * 64 + j * 8 + 2 * (lane & 3);
#pragma unroll
                for (int hh = 0; hh < 2; hh++) {
                    int r = r0 + hh * 8;
                    if (r < cnt) {
                        float2 ca = *(const float2*)(CA + (size_t)r * Nn + col);
                        float h0 = silu(ca.x) * acc[mt][j][2 * hh];
                        float h1 = silu(ca.y) * acc[mt][j][2 * hh + 1];
                        uint32_t hp = pack_bf2(h0, h1);
                        *(uint32_t*)(Hh + (size_t)r * Nn + col) = hp;
                        if (NSPLIT == 3) {
                            float2 f = unpack_bf2(hp);
                            *(uint32_t*)(Hl + (size_t)r * Nn + col) = pack_bf2(h0 - f.x, h1 - f.y);
                        }
                    }
                }
            }
        }
    }
}

// ---------------- final combine: out[t] = sum_k w_k * val_k ----------------
__global__ void combine_kernel(const float* __restrict__ x, const float* __restrict__ gamma,
                               float* __restrict__ out) {
    size_t idx = (size_t)blockIdx.x * 256u + threadIdx.x;   // over NT*DD/4
    int t = (int)(idx >> 8);
    int d = (int)(idx & 255) * 4;
    float4 xv = ((const float4*)x)[idx];
    float4 res = make_float4(0.f, 0.f, 0.f, 0.f);
#pragma unroll
    for (int k = 0; k < 2; k++) {
        int e = g_te[t][k];
        int s = g_ts[t][k];
        float w = g_tw[t][k];
        size_t base = ((size_t)e * NT + s) * DD + d;
        float4 y = *(const float4*)((const float*)(g_scratch + B_Y) + base);
        float4 val;
        if (e < NF) {
            uint2 hu = *(const uint2*)((const __nv_bfloat16*)(g_scratch + B_XGH) + base);
            uint2 lu = *(const uint2*)((const __nv_bfloat16*)(g_scratch + B_XGL) + base);
            float2 h0 = unpack_bf2(hu.x), h1 = unpack_bf2(hu.y);
            float2 l0 = unpack_bf2(lu.x), l1 = unpack_bf2(lu.y);
            float4 g = *(const float4*)(gamma + (size_t)e * DD + d);
            val.x = g.x * (h0.x + l0.x + y.x) + xv.x;
            val.y = g.y * (h0.y + l0.y + y.y) + xv.y;
            val.z = g.z * (h1.x + l1.x + y.z) + xv.z;
            val.w = g.w * (h1.y + l1.y + y.w) + xv.w;
        } else {
            val = y;
        }
        res.x += w * val.x; res.y += w * val.y;
        res.z += w * val.z; res.w += w * val.w;
    }
    ((float4*)out)[idx] = res;
}

// ---------------- launch ----------------
extern "C" void kernel_launch(void* const* d_in, const int* in_sizes, int n_in,
                              void* d_out, int out_size) {
    const float* x          = (const float*)d_in[0];
    const float* router_w   = (const float*)d_in[1];
    const float* frac_rms   = (const float*)d_in[2];
    const float* frac_w1    = (const float*)d_in[3];
    const float* frac_w2    = (const float*)d_in[4];
    const float* frac_w3    = (const float*)d_in[5];
    const float* frac_gamma = (const float*)d_in[6];
    const float* sw_w1      = (const float*)d_in[7];
    const float* sw_w2      = (const float*)d_in[8];
    const float* sw_w3      = (const float*)d_in[9];
    float* out = (float*)d_out;
    (void)in_sizes; (void)n_in; (void)out_size;

    constexpr int SM3 = 3 * (2 * 10240 + 2 * 20480);  // 184320
    constexpr int SM1 = 5 * (10240 + 20480);          // 153600
    cudaFuncSetAttribute(gemm_cp<3,0>, cudaFuncAttributeMaxDynamicSharedMemorySize, SM3);
    cudaFuncSetAttribute(gemm_cp<3,1>, cudaFuncAttributeMaxDynamicSharedMemorySize, SM3);
    cudaFuncSetAttribute(gemm_cp<1,0>, cudaFuncAttributeMaxDynamicSharedMemorySize, SM1);
    cudaFuncSetAttribute(gemm_cp<1,1>, cudaFuncAttributeMaxDynamicSharedMemorySize, SM1);

    reset_cnt<<<1, 32>>>();
    router_kernel<<<NT / 8, 256>>>(x, router_w);
    gather_kernel<<<dim3(NT, NE), 256>>>(x, frac_rms);

    conv_frac<<<dim3((int)(SZ_WF / 2 / 2048), 3), 256>>>(frac_w1, frac_w3, frac_w2);
    conv_sw<<<dim3((int)(SZ_WS / 2 / 2048), 3), 256>>>(sw_w1, sw_w3, sw_w2);

    // gate GEMMs (w1): write fp32 CA
    gemm_cp<1,0><<<dim3(HFd / 256, NT / 128, NF), 512, SM1>>>(
        B_XGH, B_XGH, (size_t)NT * DD,
        B_WF1H, B_WF1H, (size_t)HFd * DD,
        B_CAF, 0, 0, (size_t)NT * HFd, 0, DD, HFd);
    gemm_cp<3,0><<<dim3(HSd / 256, NT / 128, 4), 512, SM3>>>(
        B_XGH + (size_t)4 * NT * DD * 2, B_XGL + (size_t)4 * NT * DD * 2, (size_t)NT * DD,
        B_WS1H, B_WS1L, (size_t)HSd * DD,
        B_CAS, 0, 0, (size_t)NT * HSd, 4, DD, HSd);

    // value GEMMs (w3) with fused silu epilogue -> bf16 h planes
    gemm_cp<1,1><<<dim3(HFd / 256, NT / 128, NF), 512, SM1>>>(
        B_XGH, B_XGH, (size_t)NT * DD,
        B_WF3H, B_WF3H, (size_t)HFd * DD,
        B_CAF, B_HFH, B_HFH, (size_t)NT * HFd, 0, DD, HFd);
    gemm_cp<3,1><<<dim3(HSd / 256, NT / 128, 4), 512, SM3>>>(
        B_XGH + (size_t)4 * NT * DD * 2, B_XGL + (size_t)4 * NT * DD * 2, (size_t)NT * DD,
        B_WS3H, B_WS3L, (size_t)HSd * DD,
        B_CAS, B_HSH, B_HSL, (size_t)NT * HSd, 4, DD, HSd);

    // down projections -> fp32 Y
    gemm_cp<1,0><<<dim3(DD / 256, NT / 128, NF), 512, SM1>>>(
        B_HFH, B_HFH, (size_t)NT * HFd,
        B_WF2H, B_WF2H, (size_t)DD * HFd,
        B_Y, 0, 0, (size_t)NT * DD, 0, HFd, DD);
    gemm_cp<3,0><<<dim3(DD / 256, NT / 128, 4), 512, SM3>>>(
        B_HSH, B_HSL, (size_t)NT * HSd,
        B_WS2H, B_WS2L, (size_t)DD * HSd,
        B_Y + (size_t)4 * NT * DD * 4, 0, 0, (size_t)NT * DD, 4, HSd, DD);

    combine_kernel<<<(NT * DD / 4) / 256, 256>>>(x, frac_gamma, out);
}

// round 7
// speedup vs baseline: 3.5572x; 1.0359x over previous
#include <cuda_runtime.h>
#include <cuda_bf16.h>
#include <cstdint>
#include <math.h>

#define NT  4096
#define DD  1024
#define HFd 2048
#define HSd 4096
#define NE  8
#define NF  4

// ---------------- routing state ----------------
__device__ int   g_cnt[NE];
__device__ int   g_idx[NE][NT];       // slot -> token
__device__ int   g_te[NT][2];         // token -> expert
__device__ int   g_ts[NT][2];         // token -> slot
__device__ float g_tw[NT][2];         // token -> weight

// ---------------- scratch layout (bytes) ----------------
constexpr size_t B_XGH = 0;                                   // [NE][NT][DD] bf16 hi
constexpr size_t B_XGL = B_XGH + (size_t)NE * NT * DD * 2;    // bf16 lo
constexpr size_t B_WF1H = B_XGL + (size_t)NE * NT * DD * 2;   // frac weights hi only
constexpr size_t SZ_WF = (size_t)NF * HFd * DD * 2;
constexpr size_t B_WF3H = B_WF1H + SZ_WF;
constexpr size_t B_WF2H = B_WF3H + SZ_WF;
constexpr size_t SZ_WS = (size_t)4 * HSd * DD * 2;
constexpr size_t B_WS1H = B_WF2H + SZ_WF;
constexpr size_t B_WS1L = B_WS1H + SZ_WS;
constexpr size_t B_WS3H = B_WS1L + SZ_WS;
constexpr size_t B_WS3L = B_WS3H + SZ_WS;
constexpr size_t B_WS2H = B_WS3L + SZ_WS;
constexpr size_t B_WS2L = B_WS2H + SZ_WS;
constexpr size_t B_HFH  = B_WS2L + SZ_WS;                     // frac act hi only
constexpr size_t B_HSH  = B_HFH + (size_t)NF * NT * HFd * 2;  // switch act hi/lo
constexpr size_t B_HSL  = B_HSH + (size_t)4 * NT * HSd * 2;
constexpr size_t B_Y    = B_HSL + (size_t)4 * NT * HSd * 2;   // fp32 down-proj out
constexpr size_t SCRATCH_BYTES = B_Y + (size_t)NE * NT * DD * 4;
__device__ __align__(1024) unsigned char g_scratch[SCRATCH_BYTES];

// ---------------- PTX helpers ----------------
__device__ __forceinline__ uint32_t smem_u32(const void* p) {
    uint32_t a;
    asm("{ .reg .u64 t; cvta.to.shared.u64 t, %1; cvt.u32.u64 %0, t; }" : "=r"(a) : "l"(p));
    return a;
}
__device__ __forceinline__ uint64_t gbl_u64(const void* p) {
    uint64_t a;
    asm("cvta.to.global.u64 %0, %1;" : "=l"(a) : "l"(p));
    return a;
}
__device__ __forceinline__ void cpa16(uint32_t s, uint64_t g) {
    asm volatile("cp.async.cg.shared.global [%0], [%1], 16;" :: "r"(s), "l"(g) : "memory");
}
__device__ __forceinline__ void cpa_commit() {
    asm volatile("cp.async.commit_group;" ::: "memory");
}
template<int N>
__device__ __forceinline__ void cpa_wait() {
    asm volatile("cp.async.wait_group %0;" :: "n"(N) : "memory");
}
__device__ __forceinline__ void ldm4(uint32_t* r, uint32_t addr) {
    asm volatile("ldmatrix.sync.aligned.m8n8.x4.shared.b16 {%0,%1,%2,%3}, [%4];"
        : "=r"(r[0]), "=r"(r[1]), "=r"(r[2]), "=r"(r[3]) : "r"(addr));
}
__device__ __forceinline__ void mma16816(float* d, const uint32_t* a, uint32_t b0, uint32_t b1) {
    asm volatile("mma.sync.aligned.m16n8k16.row.col.f32.bf16.bf16.f32 "
        "{%0,%1,%2,%3}, {%4,%5,%6,%7}, {%8,%9}, {%0,%1,%2,%3};"
        : "+f"(d[0]), "+f"(d[1]), "+f"(d[2]), "+f"(d[3])
        : "r"(a[0]), "r"(a[1]), "r"(a[2]), "r"(a[3]), "r"(b0), "r"(b1));
}
__device__ __forceinline__ uint32_t pack_bf2(float x, float y) {
    union { __nv_bfloat162 h; uint32_t u; } c;
    c.h = __float22bfloat162_rn(make_float2(x, y));
    return c.u;
}
__device__ __forceinline__ float2 unpack_bf2(uint32_t u) {
    union { uint32_t v; __nv_bfloat162 h; } c; c.v = u;
    return __bfloat1622float2(c.h);
}
__device__ __forceinline__ float silu(float a) { return a / (1.f + expf(-a)); }

// ---------------- reset counts ----------------
__global__ void reset_cnt() {
    if (threadIdx.x < NE) g_cnt[threadIdx.x] = 0;
}

// ---------------- router ----------------
__global__ void router_kernel(const float* __restrict__ x, const float* __restrict__ rw) {
    int gw = (int)((blockIdx.x * blockDim.x + threadIdx.x) >> 5);
    int lane = threadIdx.x & 31;
    if (gw >= NT) return;
    const float* xr = x + (size_t)gw * DD;
    float l[NE];
#pragma unroll
    for (int e = 0; e < NE; e++) {
        const float* wr = rw + (size_t)e * DD;
        float s = 0.f;
        for (int d = lane; d < DD; d += 32) s = fmaf(xr[d], wr[d], s);
#pragma unroll
        for (int o = 16; o; o >>= 1) s += __shfl_xor_sync(0xffffffffu, s, o);
        l[e] = s;
    }
    if (lane == 0) {
        float m = l[0];
#pragma unroll
        for (int e = 1; e < NE; e++) m = fmaxf(m, l[e]);
        float w[NE], sum = 0.f;
#pragma unroll
        for (int e = 0; e < NE; e++) { w[e] = expf(l[e] - m); sum += w[e]; }
        float inv = 1.f / sum;
#pragma unroll
        for (int e = 0; e < NE; e++) w[e] *= inv;
        int i1 = 0;
#pragma unroll
        for (int e = 1; e < NE; e++) if (w[e] > w[i1]) i1 = e;
        int i2 = (i1 == 0) ? 1 : 0;
#pragma unroll
        for (int e = 0; e < NE; e++) if (e != i1 && w[e] > w[i2]) i2 = e;
        float tw = fmaxf(w[i1] + w[i2], 1e-9f);
        int p1 = atomicAdd(&g_cnt[i1], 1);
        g_idx[i1][p1] = gw;
        int p2 = atomicAdd(&g_cnt[i2], 1);
        g_idx[i2][p2] = gw;
        g_te[gw][0] = i1; g_ts[gw][0] = p1; g_tw[gw][0] = w[i1] / tw;
        g_te[gw][1] = i2; g_ts[gw][1] = p2; g_tw[gw][1] = w[i2] / tw;
    }
}

// ---------------- gather: RMSNorm / copy -> bf16 hi/lo planes ----------------
__global__ void gather_kernel(const float* __restrict__ x, const float* __restrict__ frms) {
    int e = blockIdx.y;
    int s = blockIdx.x;
    if (s >= g_cnt[e]) return;
    int t = g_idx[e][s];
    int tid = threadIdx.x;
    float4 v = ((const float4*)(x + (size_t)t * DD))[tid];
    float o0 = v.x, o1 = v.y, o2 = v.z, o3 = v.w;
    if (e < NF) {
        float ss = v.x * v.x + v.y * v.y + v.z * v.z + v.w * v.w;
#pragma unroll
        for (int o = 16; o; o >>= 1) ss += __shfl_xor_sync(0xffffffffu, ss, o);
        __shared__ float red[8];
        if ((tid & 31) == 0) red[tid >> 5] = ss;
        __syncthreads();
        if (tid < 8) {
            float r = red[tid];
#pragma unroll
            for (int o = 4; o; o >>= 1) r += __shfl_xor_sync(0x000000ffu, r, o);
            if (tid == 0) red[0] = r;
        }
        __syncthreads();
        float scale = rsqrtf(red[0] * (1.f / DD) + 1e-6f);
        float4 g = ((const float4*)(frms + (size_t)e * DD))[tid];
        o0 = v.x * scale * g.x; o1 = v.y * scale * g.y;
        o2 = v.z * scale * g.z; o3 = v.w * scale * g.w;
    }
    size_t base = ((size_t)e * NT + s) * DD + (size_t)tid * 4;
    uint32_t h0 = pack_bf2(o0, o1), h1 = pack_bf2(o2, o3);
    float2 f0 = unpack_bf2(h0), f1 = unpack_bf2(h1);
    uint32_t l0 = pack_bf2(o0 - f0.x, o1 - f0.y), l1 = pack_bf2(o2 - f1.x, o3 - f1.y);
    *(uint2*)((__nv_bfloat16*)(g_scratch + B_XGH) + base) = make_uint2(h0, h1);
    *(uint2*)((__nv_bfloat16*)(g_scratch + B_XGL) + base) = make_uint2(l0, l1);
}

// ---------------- weight fp32 -> bf16 conversions ----------------
__global__ void conv_frac(const float* __restrict__ w1, const float* __restrict__ w3,
                          const float* __restrict__ w2) {
    int z = blockIdx.y;
    const float* src = (z == 0) ? w1 : (z == 1) ? w3 : w2;
    size_t offH = (z == 0) ? B_WF1H : (z == 1) ? B_WF3H : B_WF2H;
    size_t i = ((size_t)blockIdx.x * 256u + threadIdx.x) * 8;
    float4 v0 = *(const float4*)(src + i);
    float4 v1 = *(const float4*)(src + i + 4);
    uint4 H = make_uint4(pack_bf2(v0.x, v0.y), pack_bf2(v0.z, v0.w),
                         pack_bf2(v1.x, v1.y), pack_bf2(v1.z, v1.w));
    *(uint4*)((__nv_bfloat16*)(g_scratch + offH) + i) = H;
}
__global__ void conv_sw(const float* __restrict__ w1, const float* __restrict__ w3,
                        const float* __restrict__ w2) {
    int z = blockIdx.y;
    const float* src = (z == 0) ? w1 : (z == 1) ? w3 : w2;
    size_t offH = (z == 0) ? B_WS1H : (z == 1) ? B_WS3H : B_WS2H;
    size_t offL = (z == 0) ? B_WS1L : (z == 1) ? B_WS3L : B_WS2L;
    size_t i = ((size_t)blockIdx.x * 256u + threadIdx.x) * 8;
    float4 v0 = *(const float4*)(src + i);
    float4 v1 = *(const float4*)(src + i + 4);
    float v[8] = {v0.x, v0.y, v0.z, v0.w, v1.x, v1.y, v1.z, v1.w};
    uint32_t H[4], L[4];
#pragma unroll
    for (int j = 0; j < 4; j++) {
        H[j] = pack_bf2(v[2 * j], v[2 * j + 1]);
        float2 f = unpack_bf2(H[j]);
        L[j] = pack_bf2(v[2 * j] - f.x, v[2 * j + 1] - f.y);
    }
    *(uint4*)((__nv_bfloat16*)(g_scratch + offH) + i) = make_uint4(H[0], H[1], H[2], H[3]);
    *(uint4*)((__nv_bfloat16*)(g_scratch + offL) + i) = make_uint4(L[0], L[1], L[2], L[3]);
}

// ---------------- cp.async multi-stage tensor-core GEMM ----------------
// CTA tile 128 x (128+128): B smem rows 0..127 from B0, 128..255 from B1.
// FUSE=1: B0 = w1 (gate), B1 = w3 (value), same n-range; epilogue computes
//         h = silu(gate)*val in registers and writes bf16 h planes (Nn cols).
// FUSE=0: B0/B1 = consecutive 128-row bands of the same weight (plain 128x256
//         GEMM); epilogue writes fp32 C.
#define SROW    80
#define APLANE  10240u
#define BPLANE  20480u

template<int NSPLIT, int FUSE>
__global__ void __launch_bounds__(512, 1)
gemm_cp(size_t oAh, size_t oAl, size_t strideA,
        size_t oB0h, size_t oB0l, size_t oB1h, size_t oB1l, size_t strideB,
        size_t oC, size_t oHl, size_t strideC,
        int cntBase, int K, int Nn)
{
    constexpr int STAGES = (NSPLIT == 3) ? 3 : 5;
    constexpr uint32_t OFFB = (NSPLIT == 3) ? 2 * APLANE : APLANE;
    constexpr uint32_t STG = (NSPLIT == 3) ? (2 * APLANE + 2 * BPLANE) : (APLANE + BPLANE);

    const int e = blockIdx.z;
    const int cnt = g_cnt[cntBase + e];
    const int m0 = blockIdx.y * 128;
    if (m0 >= cnt) return;
    const int n0 = blockIdx.x * (FUSE ? 128 : 256);

    const __nv_bfloat16* Ahi = (const __nv_bfloat16*)(g_scratch + oAh) + (size_t)e * strideA;
    const __nv_bfloat16* Alo = (const __nv_bfloat16*)(g_scratch + oAl) + (size_t)e * strideA;
    const __nv_bfloat16* B0hi = (const __nv_bfloat16*)(g_scratch + oB0h) + (size_t)e * strideB;
    const __nv_bfloat16* B0lo = (const __nv_bfloat16*)(g_scratch + oB0l) + (size_t)e * strideB;
    const __nv_bfloat16* B1hi = (const __nv_bfloat16*)(g_scratch + oB1h) + (size_t)e * strideB;
    const __nv_bfloat16* B1lo = (const __nv_bfloat16*)(g_scratch + oB1l) + (size_t)e * strideB;

    extern __shared__ char smem[];
    const uint32_t sb = smem_u32(smem);

    const int tid  = threadIdx.x;
    const int lane = tid & 31;
    const int wid  = tid >> 5;
    const int mr   = wid & 3;
    const int nc   = wid >> 2;

    const int row = tid >> 2;
    const int grp = tid & 3;
    const int nB1 = FUSE ? n0 : n0 + 128;
    const uint64_t gAh = gbl_u64(Ahi + (size_t)(m0 + row) * K + grp * 8);
    const uint64_t gAl = gbl_u64(Alo + (size_t)(m0 + row) * K + grp * 8);
    const uint64_t gB0h = gbl_u64(B0hi + (size_t)(n0 + row) * K + grp * 8);
    const uint64_t gB1h = gbl_u64(B1hi + (size_t)(nB1 + row) * K + grp * 8);
    const uint64_t gB0l = gbl_u64(B0lo + (size_t)(n0 + row) * K + grp * 8);
    const uint64_t gB1l = gbl_u64(B1lo + (size_t)(nB1 + row) * K + grp * 8);
    const uint32_t sA  = (uint32_t)row * SROW + grp * 16;
    const uint32_t sB0 = OFFB + (uint32_t)row * SROW + grp * 16;
    const uint32_t sB1 = sB0 + 128u * SROW;

    const uint32_t aL = (uint32_t)(mr * 32 + (lane & 15)) * SROW + ((lane >> 4) * 16);
    const int bnoff = (lane & 7) + ((lane >> 4) << 3);
    const uint32_t bLn = OFFB + (uint32_t)bnoff * SROW + (((lane >> 3) & 1) * 16);

    float acc[2][8][4];
#pragma unroll
    for (int i = 0; i < 2; i++)
#pragma unroll
        for (int j = 0; j < 8; j++)
#pragma unroll
            for (int q = 0; q < 4; q++) acc[i][j][q] = 0.f;

    const int nst = K >> 5;

    auto issue = [&](int kc, uint32_t base) {
        uint64_t d = (uint64_t)kc * 64;
        cpa16(base + sA, gAh + d);
        cpa16(base + sB0, gB0h + d);
        cpa16(base + sB1, gB1h + d);
        if (NSPLIT == 3) {
            cpa16(base + sA + APLANE, gAl + d);
            cpa16(base + sB0 + BPLANE, gB0l + d);
            cpa16(base + sB1 + BPLANE, gB1l + d);
        }
    };

#pragma unroll
    for (int s = 0; s < STAGES - 1; s++) {
        issue(s, sb + (uint32_t)s * STG);
        cpa_commit();
    }

    int slot = 0, wslot = STAGES - 1;
    for (int kc = 0; kc < nst; kc++) {
        cpa_wait<STAGES - 2>();
        __syncthreads();
        const int knext = kc + STAGES - 1;
        if (knext < nst) issue(knext, sb + (uint32_t)wslot * STG);
        cpa_commit();

        const uint32_t base = sb + (uint32_t)slot * STG;
#pragma unroll
        for (int k16 = 0; k16 < 2; k16++) {
            uint32_t ah[2][4], al[2][4];
#pragma unroll
            for (int mt = 0; mt < 2; mt++) {
                ldm4(ah[mt], base + aL + (uint32_t)(mt * 16) * SROW + k16 * 32);
                if (NSPLIT == 3)
                    ldm4(al[mt], base + aL + APLANE + (uint32_t)(mt * 16) * SROW + k16 * 32);
            }
#pragma unroll
            for (int np = 0; np < 4; np++) {
                // FUSE: np 0,1 -> gate rows (nc*32 + np*16); np 2,3 -> val rows (128 + nc*32 + (np-2)*16)
                const uint32_t brow = FUSE
                    ? (uint32_t)((np < 2) ? (nc * 32 + np * 16) : (128 + nc * 32 + (np - 2) * 16))
                    : (uint32_t)(nc * 64 + np * 16);
                uint32_t bh[4], bl[4];
                ldm4(bh, base + bLn + brow * SROW + k16 * 32);
                if (NSPLIT == 3)
                    ldm4(bl, base + bLn + BPLANE + brow * SROW + k16 * 32);
#pragma unroll
                for (int mt = 0; mt < 2; mt++)
#pragma unroll
                    for (int s2 = 0; s2 < 2; s2++) {
                        float* d = acc[mt][np * 2 + s2];
                        mma16816(d, ah[mt], bh[2 * s2], bh[2 * s2 + 1]);
                        if (NSPLIT == 3) {
                            mma16816(d, ah[mt], bl[2 * s2], bl[2 * s2 + 1]);
                            mma16816(d, al[mt], bh[2 * s2], bh[2 * s2 + 1]);
                        }
                    }
            }
        }
        slot = (slot + 1 < STAGES) ? slot + 1 : 0;
        wslot = (wslot + 1 < STAGES) ? wslot + 1 : 0;
    }

    // ---------------- epilogue ----------------
    if (FUSE == 0) {
        float* C = (float*)(g_scratch + oC) + (size_t)e * strideC;
#pragma unroll
        for (int mt = 0; mt < 2; mt++) {
            int r0 = m0 + mr * 32 + mt * 16 + (lane >> 2);
#pragma unroll
            for (int j = 0; j < 8; j++) {
                int col = n0 + nc * 64 + j * 8 + 2 * (lane & 3);
                if (r0 < cnt)
                    *(float2*)(C + (size_t)r0 * Nn + col) = make_float2(acc[mt][j][0], acc[mt][j][1]);
                if (r0 + 8 < cnt)
                    *(float2*)(C + (size_t)(r0 + 8) * Nn + col) = make_float2(acc[mt][j][2], acc[mt][j][3]);
            }
        }
    } else {
        __nv_bfloat16* Hh = (__nv_bfloat16*)(g_scratch + oC) + (size_t)e * strideC;
        __nv_bfloat16* Hl = (__nv_bfloat16*)(g_scratch + oHl) + (size_t)e * strideC;
#pragma unroll
        for (int mt = 0; mt < 2; mt++) {
            int r0 = m0 + mr * 32 + mt * 16 + (lane >> 2);
#pragma unroll
            for (int j = 0; j < 4; j++) {
                int col = n0 + nc * 32 + j * 8 + 2 * (lane & 3);
#pragma unroll
                for (int hh = 0; hh < 2; hh++) {
                    int r = r0 + hh * 8;
                    if (r < cnt) {
                        float g0 = acc[mt][j][2 * hh],     g1 = acc[mt][j][2 * hh + 1];
                        float v0 = acc[mt][j + 4][2 * hh], v1 = acc[mt][j + 4][2 * hh + 1];
                        float h0 = silu(g0) * v0;
                        float h1 = silu(g1) * v1;
                        uint32_t hp = pack_bf2(h0, h1);
                        *(uint32_t*)(Hh + (size_t)r * Nn + col) = hp;
                        if (NSPLIT == 3) {
                            float2 f = unpack_bf2(hp);
                            *(uint32_t*)(Hl + (size_t)r * Nn + col) = pack_bf2(h0 - f.x, h1 - f.y);
                        }
                    }
                }
            }
        }
    }
}

// ---------------- final combine: out[t] = sum_k w_k * val_k ----------------
__global__ void combine_kernel(const float* __restrict__ x, const float* __restrict__ gamma,
                               float* __restrict__ out) {
    size_t idx = (size_t)blockIdx.x * 256u + threadIdx.x;   // over NT*DD/4
    int t = (int)(idx >> 8);
    int d = (int)(idx & 255) * 4;
    float4 xv = ((const float4*)x)[idx];
    float4 res = make_float4(0.f, 0.f, 0.f, 0.f);
#pragma unroll
    for (int k = 0; k < 2; k++) {
        int e = g_te[t][k];
        int s = g_ts[t][k];
        float w = g_tw[t][k];
        size_t base = ((size_t)e * NT + s) * DD + d;
        float4 y = *(const float4*)((const float*)(g_scratch + B_Y) + base);
        float4 val;
        if (e < NF) {
            uint2 hu = *(const uint2*)((const __nv_bfloat16*)(g_scratch + B_XGH) + base);
            uint2 lu = *(const uint2*)((const __nv_bfloat16*)(g_scratch + B_XGL) + base);
            float2 h0 = unpack_bf2(hu.x), h1 = unpack_bf2(hu.y);
            float2 l0 = unpack_bf2(lu.x), l1 = unpack_bf2(lu.y);
            float4 g = *(const float4*)(gamma + (size_t)e * DD + d);
            val.x = g.x * (h0.x + l0.x + y.x) + xv.x;
            val.y = g.y * (h0.y + l0.y + y.y) + xv.y;
            val.z = g.z * (h1.x + l1.x + y.z) + xv.z;
            val.w = g.w * (h1.y + l1.y + y.w) + xv.w;
        } else {
            val = y;
        }
        res.x += w * val.x; res.y += w * val.y;
        res.z += w * val.z; res.w += w * val.w;
    }
    ((float4*)out)[idx] = res;
}

// ---------------- launch ----------------
extern "C" void kernel_launch(void* const* d_in, const int* in_sizes, int n_in,
                              void* d_out, int out_size) {
    const float* x          = (const float*)d_in[0];
    const float* router_w   = (const float*)d_in[1];
    const float* frac_rms   = (const float*)d_in[2];
    const float* frac_w1    = (const float*)d_in[3];
    const float* frac_w2    = (const float*)d_in[4];
    const float* frac_w3    = (const float*)d_in[5];
    const float* frac_gamma = (const float*)d_in[6];
    const float* sw_w1      = (const float*)d_in[7];
    const float* sw_w2      = (const float*)d_in[8];
    const float* sw_w3      = (const float*)d_in[9];
    float* out = (float*)d_out;
    (void)in_sizes; (void)n_in; (void)out_size;

    constexpr int SM3 = 3 * (2 * 10240 + 2 * 20480);  // 184320
    constexpr int SM1 = 5 * (10240 + 20480);          // 153600
    cudaFuncSetAttribute(gemm_cp<3,0>, cudaFuncAttributeMaxDynamicSharedMemorySize, SM3);
    cudaFuncSetAttribute(gemm_cp<3,1>, cudaFuncAttributeMaxDynamicSharedMemorySize, SM3);
    cudaFuncSetAttribute(gemm_cp<1,0>, cudaFuncAttributeMaxDynamicSharedMemorySize, SM1);
    cudaFuncSetAttribute(gemm_cp<1,1>, cudaFuncAttributeMaxDynamicSharedMemorySize, SM1);

    reset_cnt<<<1, 32>>>();
    router_kernel<<<NT / 8, 256>>>(x, router_w);
    gather_kernel<<<dim3(NT, NE), 256>>>(x, frac_rms);

    conv_frac<<<dim3((int)(SZ_WF / 2 / 2048), 3), 256>>>(frac_w1, frac_w3, frac_w2);
    conv_sw<<<dim3((int)(SZ_WS / 2 / 2048), 3), 256>>>(sw_w1, sw_w3, sw_w2);

    // fused up GEMMs: h = silu(A@w1^T) * (A@w3^T) -> bf16 h planes
    gemm_cp<1,1><<<dim3(HFd / 128, NT / 128, NF), 512, SM1>>>(
        B_XGH, B_XGH, (size_t)NT * DD,
        B_WF1H, B_WF1H, B_WF3H, B_WF3H, (size_t)HFd * DD,
        B_HFH, B_HFH, (size_t)NT * HFd, 0, DD, HFd);
    gemm_cp<3,1><<<dim3(HSd / 128, NT / 128, 4), 512, SM3>>>(
        B_XGH + (size_t)4 * NT * DD * 2, B_XGL + (size_t)4 * NT * DD * 2, (size_t)NT * DD,
        B_WS1H, B_WS1L, B_WS3H, B_WS3L, (size_t)HSd * DD,
        B_HSH, B_HSL, (size_t)NT * HSd, 4, DD, HSd);

    // down projections -> fp32 Y
    gemm_cp<1,0><<<dim3(DD / 256, NT / 128, NF), 512, SM1>>>(
        B_HFH, B_HFH, (size_t)NT * HFd,
        B_WF2H, B_WF2H, B_WF2H, B_WF2H, (size_t)DD * HFd,
        B_Y, 0, (size_t)NT * DD, 0, HFd, DD);
    gemm_cp<3,0><<<dim3(DD / 256, NT / 128, 4), 512, SM3>>>(
        B_HSH, B_HSL, (size_t)NT * HSd,
        B_WS2H, B_WS2L, B_WS2H, B_WS2L, (size_t)DD * HSd,
        B_Y + (size_t)4 * NT * DD * 4, 0, (size_t)NT * DD, 4, HSd, DD);

    combine_kernel<<<(NT * DD / 4) / 256, 256>>>(x, frac_gamma, out);
}